// round 13
// baseline (speedup 1.0000x reference)
#include <cuda_runtime.h>
#include <math.h>

// ---------------- problem constants ----------------
#define NB 8
#define NS 1024
#define ND 1152
#define NH 16
#define NHD 72
#define NL 32
#define NR 36
#define NT (NB*NS)          // 8192 tokens
#define KW (ND/4)           // 288 packed int32 words per row
#define BHS (NS*NHD)        // 73728 floats per (b,h) of q/k/v
#define QSTR 76             // Q/K/V smem row stride (conflict-free, 16B-aligned)
#define PSTR 68             // Ps row stride: 16B-aligned rows -> float4 phase-B reads

typedef unsigned long long ull;

// ---------------- device scratch (static; no allocations) ----------------
__device__ __align__(16) float  g_invA[NL*NL];
__device__ __align__(16) float  g_invB[NR*NR];
__device__ __align__(16) float  g_invVC[NHD*NHD];
__device__ __align__(16) float  g_invO[NH*NH];
__device__ double g_gj[4][72*144];

__device__ __align__(16) int    g_wq[3456*KW];
__device__ __align__(16) float  g_ws[3456];
__device__ __align__(16) float  g_bias[3456];
__device__ __align__(16) float  g_WvT[ND*ND];
__device__ __align__(16) int    g_woq[ND*KW];
__device__ __align__(16) float  g_wos[ND];

__device__ __align__(16) int    g_xq[NT*KW];
__device__ __align__(16) float  g_xs[NT];
__device__ __align__(16) float  g_q[NT*ND];        // (B,H,S,HD)
__device__ __align__(16) float  g_k[NT*ND];
__device__ __align__(16) float  g_v[NT*ND];
__device__ __align__(16) float  g_ctx[NT*ND];      // (B,S,H,HD)
__device__ __align__(16) int    g_cq[NT*KW];
__device__ __align__(16) float  g_cs[NT];

// ---------------- f32x2 packed primitives (sm_103a) ----------------
__device__ __forceinline__ ull packf2(float lo, float hi) {
    ull r; asm("mov.b64 %0, {%1, %2};" : "=l"(r) : "f"(lo), "f"(hi)); return r;
}
__device__ __forceinline__ void unpackf2(ull v, float& lo, float& hi) {
    asm("mov.b64 {%0, %1}, %2;" : "=f"(lo), "=f"(hi) : "l"(v));
}
__device__ __forceinline__ void fma2(ull& d, ull a, ull b) {
    asm("fma.rn.f32x2 %0, %1, %2, %3;" : "=l"(d) : "l"(a), "l"(b), "l"(d));
}
__device__ __forceinline__ void mul2(ull& d, ull a) {
    asm("mul.rn.f32x2 %0, %1, %2;" : "=l"(d) : "l"(d), "l"(a));
}

// ---------------- compensated fp32 (double-float) primitives ----------------
__device__ __forceinline__ void df_mac(float a, float b, float& s, float& c) {
    float p = a * b;
    float e = fmaf(a, b, -p);
    float t = s + p;
    float bb = t - s;
    float err = (s - (t - bb)) + (p - bb);
    s = t;
    c += err + e;
}
__device__ __forceinline__ void df_mac2(float ahi, float alo, float b, float& s, float& c) {
    float p = ahi * b;
    float e = fmaf(ahi, b, -p);
    e = fmaf(alo, b, e);
    float t = s + p;
    float bb = t - s;
    float err = (s - (t - bb)) + (p - bb);
    s = t;
    c += err + e;
}
__device__ __forceinline__ float df_dequant(float a, float sx, float sw, float bias) {
    float p1 = a * sx;  float e1 = fmaf(a, sx, -p1);
    float p2 = p1 * sw; float e2 = fmaf(p1, sw, -p2);
    e2 = fmaf(e1, sw, e2);
    float t = p2 + bias;
    float bb = t - p2;
    float err = (p2 - (t - bb)) + (bias - bb);
    return t + (err + e2);
}

// ---------------- helpers ----------------
__device__ __forceinline__ int pack4q(float a, float b, float c, float d,
                                      float s, float lo, float hi) {
    int ia = (int)fminf(fmaxf(rintf(__fdiv_rn(a, s)), lo), hi);
    int ib = (int)fminf(fmaxf(rintf(__fdiv_rn(b, s)), lo), hi);
    int ic = (int)fminf(fmaxf(rintf(__fdiv_rn(c, s)), lo), hi);
    int id = (int)fminf(fmaxf(rintf(__fdiv_rn(d, s)), lo), hi);
    return (ia & 0xFF) | ((ib & 0xFF) << 8) | ((ic & 0xFF) << 16) | ((id & 0xFF) << 24);
}

__device__ __forceinline__ float block_max_abs_128(const float* Y, int n, int tid, float* red) {
    float mx = 0.f;
    for (int c = tid; c < n; c += 128) mx = fmaxf(mx, fabsf(Y[c]));
    red[tid] = mx;
    __syncthreads();
    for (int o = 64; o > 0; o >>= 1) {
        if (tid < o) red[tid] = fmaxf(red[tid], red[tid + o]);
        __syncthreads();
    }
    float r = red[0];
    __syncthreads();
    return r;
}

// accurate expf (Cody-Waite + deg-6 Taylor) on the FMA pipe, fast-math-immune
__device__ __forceinline__ float exp_acc(float x) {
    if (x < -87.0f) return 0.0f;
    float n = rintf(x * 1.4426950408889634f);
    float r = fmaf(-n, 0.6931471824645996f, x);
    r = fmaf(n, 1.9046542999577600e-9f, r);
    float p = 1.3888888888888889e-3f;
    p = fmaf(p, r, 8.3333333333333333e-3f);
    p = fmaf(p, r, 4.1666666666666664e-2f);
    p = fmaf(p, r, 1.6666666666666666e-1f);
    p = fmaf(p, r, 0.5f);
    p = fmaf(p, r, 1.0f);
    p = fmaf(p, r, 1.0f);
    int ni = (int)n;
    return p * __int_as_float((ni + 127) << 23);
}

// ---------------- 1) small-matrix inverses (fp64 Gauss-Jordan, tiny) ---------
__global__ void inv_kernel(const float* __restrict__ Asrc, const float* __restrict__ Bsrc,
                           const float* __restrict__ Vsrc, const float* __restrict__ Osrc) {
    int blk = blockIdx.x, tid = threadIdx.x;
    int n; const float* src; float* dst;
    if      (blk == 0) { n = NL;  src = Asrc; dst = g_invA;  }
    else if (blk == 1) { n = NR;  src = Bsrc; dst = g_invB;  }
    else if (blk == 2) { n = NHD; src = Vsrc; dst = g_invVC; }
    else               { n = NH;  src = Osrc; dst = g_invO;  }
    double* aug = g_gj[blk];
    int n2 = 2 * n;
    for (int idx = tid; idx < n * n2; idx += blockDim.x) {
        int i = idx / n2, j = idx - i * n2;
        aug[idx] = (j < n) ? (double)src[i * n + j] : ((j - n) == i ? 1.0 : 0.0);
    }
    __syncthreads();
    __shared__ int piv;
    for (int k = 0; k < n; k++) {
        if (tid == 0) {
            int p = k; double best = fabs(aug[k * n2 + k]);
            for (int i = k + 1; i < n; i++) {
                double v = fabs(aug[i * n2 + k]);
                if (v > best) { best = v; p = i; }
            }
            piv = p;
        }
        __syncthreads();
        if (piv != k) {
            for (int j = tid; j < n2; j += blockDim.x) {
                double t = aug[k * n2 + j];
                aug[k * n2 + j] = aug[piv * n2 + j];
                aug[piv * n2 + j] = t;
            }
        }
        __syncthreads();
        double pv = aug[k * n2 + k];
        __syncthreads();
        for (int j = tid; j < n2; j += blockDim.x) aug[k * n2 + j] /= pv;
        __syncthreads();
        for (int i = tid; i < n; i += blockDim.x) {
            if (i == k) continue;
            double f = aug[i * n2 + k];
            for (int j = 0; j < n2; j++) aug[i * n2 + j] -= f * aug[k * n2 + j];
        }
        __syncthreads();
    }
    for (int idx = tid; idx < n * n; idx += blockDim.x)
        dst[idx] = (float)aug[(idx / n) * n2 + n + (idx % n)];
}

// ---------------- 2) q/k/v weight kron transform (comp fp32, 3-way ILP) -----------
__global__ void wtrans_qkv_kernel(const float* __restrict__ Wq_, const float* __restrict__ bq_,
                                  const float* __restrict__ Wk_, const float* __restrict__ bk_,
                                  const float* __restrict__ Wv_, const float* __restrict__ ldg) {
    int which = blockIdx.y, i = blockIdx.x, tid = threadIdx.x;
    const float* W = (which == 0) ? Wq_ : (which == 1) ? Wk_ : Wv_;
    __shared__ float X[ND], Yf[ND];
    __shared__ float2 T1[ND];
    __shared__ float iA[NL*NL], iB[NR*NR], red[128];
    for (int c = tid; c < NL*NL; c += 128) iA[c] = g_invA[c];
    for (int c = tid; c < NR*NR; c += 128) iB[c] = g_invB[c];
    for (int c = tid; c < ND; c += 128) X[c] = W[(size_t)i * ND + c] * __frcp_rn(ldg[c]);
    __syncthreads();
    #pragma unroll
    for (int ob = 0; ob < 3; ob++) {
        int o0 = tid + ob * 384, o1 = o0 + 128, o2 = o0 + 256;
        int p0 = o0 / NR, r0 = o0 - p0 * NR;
        int p1 = o1 / NR, r1 = o1 - p1 * NR;
        int p2 = o2 / NR, r2 = o2 - p2 * NR;
        float s0 = 0.f, c0 = 0.f, s1 = 0.f, c1 = 0.f, s2 = 0.f, c2 = 0.f;
        #pragma unroll 8
        for (int l = 0; l < NL; l++) {
            df_mac(iA[p0 * NL + l], X[l * NR + r0], s0, c0);
            df_mac(iA[p1 * NL + l], X[l * NR + r1], s1, c1);
            df_mac(iA[p2 * NL + l], X[l * NR + r2], s2, c2);
        }
        T1[o0] = make_float2(s0, c0);
        T1[o1] = make_float2(s1, c1);
        T1[o2] = make_float2(s2, c2);
    }
    __syncthreads();
    #pragma unroll
    for (int ob = 0; ob < 3; ob++) {
        int o0 = tid + ob * 384, o1 = o0 + 128, o2 = o0 + 256;
        int p0 = o0 / NR, q0 = o0 - p0 * NR;
        int p1 = o1 / NR, q1 = o1 - p1 * NR;
        int p2 = o2 / NR, q2 = o2 - p2 * NR;
        float s0 = 0.f, c0 = 0.f, s1 = 0.f, c1 = 0.f, s2 = 0.f, c2 = 0.f;
        #pragma unroll 6
        for (int r = 0; r < NR; r++) {
            float2 t0 = T1[p0 * NR + r]; df_mac2(t0.x, t0.y, iB[q0 * NR + r], s0, c0);
            float2 t1 = T1[p1 * NR + r]; df_mac2(t1.x, t1.y, iB[q1 * NR + r], s1, c1);
            float2 t2 = T1[p2 * NR + r]; df_mac2(t2.x, t2.y, iB[q2 * NR + r], s2, c2);
        }
        Yf[o0] = s0 + c0; Yf[o1] = s1 + c1; Yf[o2] = s2 + c2;
    }
    __syncthreads();
    if (which == 2) {
        for (int c = tid; c < ND; c += 128) g_WvT[(size_t)i * ND + c] = Yf[c];
        return;
    }
    float mx = block_max_abs_128(Yf, ND, tid, red);
    float s = fmaxf(__fdiv_rn(mx, 7.0f), 1e-8f);
    int row = which * ND + i;
    for (int w = tid; w < KW; w += 128)
        g_wq[(size_t)row * KW + w] = pack4q(Yf[4*w], Yf[4*w+1], Yf[4*w+2], Yf[4*w+3], s, -8.f, 7.f);
    if (tid == 0) {
        g_ws[row] = s;
        g_bias[row] = (which == 0 ? bq_ : bk_)[i];
    }
}

// ---------------- 3) v weight: vc output-channel mix (9-way ILP) ----------
__global__ void wtrans_vmix_kernel(const float* __restrict__ vc, const float* __restrict__ bv) {
    int rr = blockIdx.x, tid = threadIdx.x;
    int h = rr / NHD, e = rr - h * NHD;
    __shared__ float Y[ND], red[128], vcol[NHD];
    for (int d = tid; d < NHD; d += 128) vcol[d] = vc[d * NHD + e];
    __syncthreads();
    float ys[9], yc[9];
    #pragma unroll
    for (int jj = 0; jj < 9; jj++) { ys[jj] = 0.f; yc[jj] = 0.f; }
    for (int d = 0; d < NHD; d++) {
        float vv = vcol[d];
        const float* row = &g_WvT[(size_t)(h * NHD + d) * ND];
        #pragma unroll
        for (int jj = 0; jj < 9; jj++) df_mac(row[tid + jj * 128], vv, ys[jj], yc[jj]);
    }
    #pragma unroll
    for (int jj = 0; jj < 9; jj++) Y[tid + jj * 128] = ys[jj] + yc[jj];
    __syncthreads();
    float mx = block_max_abs_128(Y, ND, tid, red);
    float s = fmaxf(__fdiv_rn(mx, 7.0f), 1e-8f);
    int row = 2 * ND + rr;
    for (int w = tid; w < KW; w += 128)
        g_wq[(size_t)row * KW + w] = pack4q(Y[4*w], Y[4*w+1], Y[4*w+2], Y[4*w+3], s, -8.f, 7.f);
    if (tid == 0) {
        g_ws[row] = s;
        double bt = 0.0;
        for (int d = 0; d < NHD; d++) bt += (double)bv[h * NHD + d] * (double)vcol[d];
        g_bias[row] = (float)bt;
    }
}

// ---------------- 4) output weight transform (comp fp32, 3-way ILP) ---------------
__global__ void wtrans_o_kernel(const float* __restrict__ Wo_) {
    int o = blockIdx.x, tid = threadIdx.x;
    __shared__ float M[ND], Yf[ND], red[128];
    __shared__ float2 T[NH*NHD];
    __shared__ float iV[NHD*NHD], iO[NH*NH];
    for (int c = tid; c < NHD*NHD; c += 128) iV[c] = g_invVC[c];
    for (int c = tid; c < NH*NH; c += 128) iO[c] = g_invO[c];
    for (int c = tid; c < ND; c += 128) M[c] = Wo_[(size_t)o * ND + c];
    __syncthreads();
    #pragma unroll
    for (int ob = 0; ob < 3; ob++) {
        int i0 = tid + ob * 384, i1 = i0 + 128, i2 = i0 + 256;
        int g0 = i0 / NHD, e0 = i0 - g0 * NHD;
        int g1 = i1 / NHD, e1 = i1 - g1 * NHD;
        int g2 = i2 / NHD, e2 = i2 - g2 * NHD;
        float s0 = 0.f, c0 = 0.f, s1 = 0.f, c1 = 0.f, s2 = 0.f, c2 = 0.f;
        #pragma unroll 8
        for (int d = 0; d < NHD; d++) {
            df_mac(M[g0 * NHD + d], iV[e0 * NHD + d], s0, c0);
            df_mac(M[g1 * NHD + d], iV[e1 * NHD + d], s1, c1);
            df_mac(M[g2 * NHD + d], iV[e2 * NHD + d], s2, c2);
        }
        T[i0] = make_float2(s0, c0);
        T[i1] = make_float2(s1, c1);
        T[i2] = make_float2(s2, c2);
    }
    __syncthreads();
    #pragma unroll
    for (int ob = 0; ob < 3; ob++) {
        int i0 = tid + ob * 384, i1 = i0 + 128, i2 = i0 + 256;
        int h0 = i0 / NHD, e0 = i0 - h0 * NHD;
        int h1 = i1 / NHD, e1 = i1 - h1 * NHD;
        int h2 = i2 / NHD, e2 = i2 - h2 * NHD;
        float s0 = 0.f, c0 = 0.f, s1 = 0.f, c1 = 0.f, s2 = 0.f, c2 = 0.f;
        #pragma unroll
        for (int g = 0; g < NH; g++) {
            float2 t0 = T[g * NHD + e0]; df_mac2(t0.x, t0.y, iO[h0 * NH + g], s0, c0);
            float2 t1 = T[g * NHD + e1]; df_mac2(t1.x, t1.y, iO[h1 * NH + g], s1, c1);
            float2 t2 = T[g * NHD + e2]; df_mac2(t2.x, t2.y, iO[h2 * NH + g], s2, c2);
        }
        Yf[i0] = s0 + c0; Yf[i1] = s1 + c1; Yf[i2] = s2 + c2;
    }
    __syncthreads();
    float mx = block_max_abs_128(Yf, ND, tid, red);
    float s = fmaxf(__fdiv_rn(mx, 7.0f), 1e-8f);
    for (int w = tid; w < KW; w += 128)
        g_woq[(size_t)o * KW + w] = pack4q(Yf[4*w], Yf[4*w+1], Yf[4*w+2], Yf[4*w+3], s, -8.f, 7.f);
    if (tid == 0) g_wos[o] = s;
}

// ---------------- 5) activation kron transform (comp fp32, 3-way ILP) + quant -----
__global__ void act_kernel(const float* __restrict__ hs, const float* __restrict__ ldg,
                           const float* __restrict__ lnA, const float* __restrict__ lnB) {
    int t = blockIdx.x, tid = threadIdx.x;
    __shared__ float X[ND], Yf[ND];
    __shared__ float2 T1[ND];
    __shared__ float A[NL*NL], Bm[NR*NR], red[128];
    for (int c = tid; c < NL*NL; c += 128) A[c] = lnA[c];
    for (int c = tid; c < NR*NR; c += 128) Bm[c] = lnB[c];
    for (int c = tid; c < ND; c += 128) X[c] = hs[(size_t)t * ND + c] * ldg[c];
    __syncthreads();
    #pragma unroll
    for (int ob = 0; ob < 3; ob++) {
        int o0 = tid + ob * 384, o1 = o0 + 128, o2 = o0 + 256;
        int p0 = o0 / NR, r0 = o0 - p0 * NR;
        int p1 = o1 / NR, r1 = o1 - p1 * NR;
        int p2 = o2 / NR, r2 = o2 - p2 * NR;
        float s0 = 0.f, c0 = 0.f, s1 = 0.f, c1 = 0.f, s2 = 0.f, c2 = 0.f;
        #pragma unroll 8
        for (int l = 0; l < NL; l++) {
            df_mac(A[l * NL + p0], X[l * NR + r0], s0, c0);
            df_mac(A[l * NL + p1], X[l * NR + r1], s1, c1);
            df_mac(A[l * NL + p2], X[l * NR + r2], s2, c2);
        }
        T1[o0] = make_float2(s0, c0);
        T1[o1] = make_float2(s1, c1);
        T1[o2] = make_float2(s2, c2);
    }
    __syncthreads();
    #pragma unroll
    for (int ob = 0; ob < 3; ob++) {
        int o0 = tid + ob * 384, o1 = o0 + 128, o2 = o0 + 256;
        int p0 = o0 / NR, q0 = o0 - p0 * NR;
        int p1 = o1 / NR, q1 = o1 - p1 * NR;
        int p2 = o2 / NR, q2 = o2 - p2 * NR;
        float s0 = 0.f, c0 = 0.f, s1 = 0.f, c1 = 0.f, s2 = 0.f, c2 = 0.f;
        #pragma unroll 6
        for (int r = 0; r < NR; r++) {
            float2 t0 = T1[p0 * NR + r]; df_mac2(t0.x, t0.y, Bm[r * NR + q0], s0, c0);
            float2 t1 = T1[p1 * NR + r]; df_mac2(t1.x, t1.y, Bm[r * NR + q1], s1, c1);
            float2 t2 = T1[p2 * NR + r]; df_mac2(t2.x, t2.y, Bm[r * NR + q2], s2, c2);
        }
        Yf[o0] = s0 + c0; Yf[o1] = s1 + c1; Yf[o2] = s2 + c2;
    }
    __syncthreads();
    float mx = block_max_abs_128(Yf, ND, tid, red);
    float s = fmaxf(__fdiv_rn(mx, 127.0f), 1e-8f);
    if (tid == 0) g_xs[t] = s;
    for (int w = tid; w < KW; w += 128)
        g_xq[(size_t)t * KW + w] = pack4q(Yf[4*w], Yf[4*w+1], Yf[4*w+2], Yf[4*w+3], s, -128.f, 127.f);
}

// ---------------- 6) dp4a GEMM (mode 0: qkv projections+scatter; mode 1: final) ----
__global__ __launch_bounds__(256) void gemm_dp4a_kernel(int mode, const float* __restrict__ bias_ext,
                                                        float* __restrict__ outp) {
    __shared__ int Xs[16][128];
    __shared__ int Wsm[16][128];
    const int*   __restrict__ Xq  = mode ? g_cq  : g_xq;
    const float* __restrict__ xs  = mode ? g_cs  : g_xs;
    const int*   __restrict__ Wp  = mode ? g_woq : g_wq;
    const float* __restrict__ wsp = mode ? g_wos : g_ws;
    int m0 = blockIdx.y * 128, n0 = blockIdx.x * 128;
    int tid = threadIdx.x;
    int acc[8][8];
    #pragma unroll
    for (int i = 0; i < 8; i++)
        #pragma unroll
        for (int j = 0; j < 8; j++) acc[i][j] = 0;
    int r = tid >> 2, wg = (tid & 3) << 2;
    int ty = tid >> 4, tx = tid & 15;
    for (int kt = 0; kt < 18; kt++) {
        #pragma unroll
        for (int half = 0; half < 2; half++) {
            int row = r + (half << 6);
            int4 xv = *(const int4*)&Xq[(size_t)(m0 + row) * KW + kt * 16 + wg];
            Xs[wg + 0][row] = xv.x; Xs[wg + 1][row] = xv.y;
            Xs[wg + 2][row] = xv.z; Xs[wg + 3][row] = xv.w;
            int4 wv = *(const int4*)&Wp[(size_t)(n0 + row) * KW + kt * 16 + wg];
            Wsm[wg + 0][row] = wv.x; Wsm[wg + 1][row] = wv.y;
            Wsm[wg + 2][row] = wv.z; Wsm[wg + 3][row] = wv.w;
        }
        __syncthreads();
        #pragma unroll 4
        for (int kk = 0; kk < 16; kk++) {
            int4 xa = *(const int4*)&Xs[kk][ty << 3];
            int4 xb = *(const int4*)&Xs[kk][(ty << 3) + 4];
            int4 wa = *(const int4*)&Wsm[kk][tx << 3];
            int4 wb = *(const int4*)&Wsm[kk][(tx << 3) + 4];
            int xv[8] = {xa.x, xa.y, xa.z, xa.w, xb.x, xb.y, xb.z, xb.w};
            int wv[8] = {wa.x, wa.y, wa.z, wa.w, wb.x, wb.y, wb.z, wb.w};
            #pragma unroll
            for (int i = 0; i < 8; i++)
                #pragma unroll
                for (int j = 0; j < 8; j++)
                    acc[i][j] = __dp4a(xv[i], wv[j], acc[i][j]);
        }
        __syncthreads();
    }
    #pragma unroll
    for (int i = 0; i < 8; i++) {
        int m = m0 + (ty << 3) + i;
        float sx = xs[m];
        #pragma unroll
        for (int j = 0; j < 8; j++) {
            int n = n0 + (tx << 3) + j;
            if (mode) {
                float val = df_dequant((float)acc[i][j], sx, wsp[n], bias_ext[n]);
                outp[(size_t)m * ND + n] = val;
            } else {
                float val = df_dequant((float)acc[i][j], sx, wsp[n], g_bias[n]);
                int which = n / ND;
                int jj = n - which * ND;
                int h = jj / NHD, hd = jj - h * NHD;
                int b = m >> 10, sidx = m & 1023;
                float* dst = (which == 0) ? g_q : (which == 1) ? g_k : g_v;
                dst[((size_t)((b << 4) + h) * NS + sidx) * NHD + hd] = val;
            }
        }
    }
}

// ---------------- 7) attention: q128 (best base), phase-B Ps via float4 ----------------
// ty = tid>>3 (0..31), tx = tid&7. q rows: i*32+ty (i 0..3), k cols: j*8+tx.
// Identical per-value arithmetic order to R8 -> bit-identical output.
__global__ __launch_bounds__(256, 2) void attn_kernel() {
    extern __shared__ float sm[];
    float* Qs   = sm;                       // 128*76
    float* Ks   = sm + 128 * QSTR;          //  64*76
    float* Vs   = Ks + 64 * QSTR;           //  64*76
    float* Ps   = Vs + 64 * QSTR;           // 128*68
    float* m_sm = Ps + 128 * PSTR;
    float* l_sm = m_sm + 128;
    float* f_sm = l_sm + 128;
    int bh = blockIdx.y, qt = blockIdx.x, tid = threadIdx.x;
    const float* Qp = g_q + (size_t)bh * BHS + (size_t)qt * 128 * NHD;
    const float* Kp = g_k + (size_t)bh * BHS;
    const float* Vp = g_v + (size_t)bh * BHS;
    for (int idx = tid; idx < 128 * 18; idx += 256) {
        int row = idx / 18, c = idx - row * 18;
        ((float4*)(Qs + row * QSTR))[c] = ((const float4*)(Qp + row * NHD))[c];
    }
    if (tid < 128) { m_sm[tid] = -1e30f; l_sm[tid] = 0.f; }
    ull acc2[4][4];
    float acc8[4];
    #pragma unroll
    for (int i = 0; i < 4; i++) {
        #pragma unroll
        for (int cp = 0; cp < 4; cp++) acc2[i][cp] = 0ull;
        acc8[i] = 0.f;
    }
    int ty = tid >> 3, tx = tid & 7;
    __syncthreads();

    for (int kt0 = 0; kt0 < NS; kt0 += 64) {
        for (int idx = tid; idx < 64 * 18; idx += 256) {
            int row = idx / 18, c = idx - row * 18;
            ((float4*)(Ks + row * QSTR))[c] = ((const float4*)(Kp + (kt0 + row) * NHD))[c];
            ((float4*)(Vs + row * QSTR))[c] = ((const float4*)(Vp + (kt0 + row) * NHD))[c];
        }
        __syncthreads();
        // ---- phase A: two passes of 4 j, accumulators paired along d ----
        #pragma unroll
        for (int pass = 0; pass < 2; pass++) {
            ull sacc[4][4];
            #pragma unroll
            for (int i = 0; i < 4; i++)
                #pragma unroll
                for (int jj = 0; jj < 4; jj++) sacc[i][jj] = 0ull;
            #pragma unroll 3
            for (int d4 = 0; d4 < 18; d4++) {
                longlong2 qv[4], kv[4];
                #pragma unroll
                for (int i = 0; i < 4; i++)
                    qv[i] = *(const longlong2*)&Qs[(i * 32 + ty) * QSTR + d4 * 4];
                #pragma unroll
                for (int jj = 0; jj < 4; jj++)
                    kv[jj] = *(const longlong2*)&Ks[((pass * 4 + jj) * 8 + tx) * QSTR + d4 * 4];
                #pragma unroll
                for (int i = 0; i < 4; i++)
                    #pragma unroll
                    for (int jj = 0; jj < 4; jj++) {
                        fma2(sacc[i][jj], (ull)qv[i].x, (ull)kv[jj].x);
                        fma2(sacc[i][jj], (ull)qv[i].y, (ull)kv[jj].y);
                    }
            }
            #pragma unroll
            for (int i = 0; i < 4; i++)
                #pragma unroll
                for (int jj = 0; jj < 4; jj++) {
                    float lo, hi;
                    unpackf2(sacc[i][jj], lo, hi);
                    Ps[(i * 32 + ty) * PSTR + (pass * 4 + jj) * 8 + tx] = lo + hi;
                }
        }
        // ---- online softmax ----
        #pragma unroll
        for (int i = 0; i < 4; i++) {
            int q = i * 32 + ty;
            float s[8];
            #pragma unroll
            for (int j = 0; j < 8; j++) s[j] = Ps[q * PSTR + j * 8 + tx];
            float rm = s[0];
            #pragma unroll
            for (int j = 1; j < 8; j++) rm = fmaxf(rm, s[j]);
            rm = fmaxf(rm, __shfl_xor_sync(0xffffffffu, rm, 1, 8));
            rm = fmaxf(rm, __shfl_xor_sync(0xffffffffu, rm, 2, 8));
            rm = fmaxf(rm, __shfl_xor_sync(0xffffffffu, rm, 4, 8));
            float mo = m_sm[q];
            float mn = fmaxf(mo, rm);
            float rs = 0.f;
            #pragma unroll
            for (int j = 0; j < 8; j++) {
                float p = exp_acc(s[j] - mn);
                Ps[q * PSTR + j * 8 + tx] = p;
                rs += p;
            }
            rs += __shfl_xor_sync(0xffffffffu, rs, 1, 8);
            rs += __shfl_xor_sync(0xffffffffu, rs, 2, 8);
            rs += __shfl_xor_sync(0xffffffffu, rs, 4, 8);
            if (tx == 0) {
                float f = exp_acc(mo - mn);
                f_sm[q] = f;
                l_sm[q] = l_sm[q] * f + rs;
                m_sm[q] = mn;
            }
        }
        __syncthreads();
        // ---- phase B: acc = acc*f + P @ V (Ps read via float4) ----
        #pragma unroll
        for (int i = 0; i < 4; i++) {
            float f = f_sm[i * 32 + ty];
            ull f2 = packf2(f, f);
            #pragma unroll
            for (int cp = 0; cp < 4; cp++) mul2(acc2[i][cp], f2);
            acc8[i] *= f;
        }
        for (int k4 = 0; k4 < 16; k4++) {
            float4 pq[4];
            #pragma unroll
            for (int i = 0; i < 4; i++)
                pq[i] = *(const float4*)&Ps[(i * 32 + ty) * PSTR + k4 * 4];
            #pragma unroll
            for (int kk = 0; kk < 4; kk++) {
                int k = k4 * 4 + kk;
                longlong2 va = *(const longlong2*)&Vs[k * QSTR + tx * 8];
                longlong2 vb = *(const longlong2*)&Vs[k * QSTR + tx * 8 + 4];
                float v8 = Vs[k * QSTR + 64 + tx];
                #pragma unroll
                for (int i = 0; i < 4; i++) {
                    float p = ((const float*)&pq[i])[kk];
                    ull p2 = packf2(p, p);
                    fma2(acc2[i][0], p2, (ull)va.x);
                    fma2(acc2[i][1], p2, (ull)va.y);
                    fma2(acc2[i][2], p2, (ull)vb.x);
                    fma2(acc2[i][3], p2, (ull)vb.y);
                    acc8[i] = fmaf(p, v8, acc8[i]);
                }
            }
        }
        __syncthreads();
    }
    // ---- write ctx (B,S,H,HD): c = tx*8 + 0..7 and 64+tx ----
    int h = bh & 15, b = bh >> 4;
    #pragma unroll
    for (int i = 0; i < 4; i++) {
        int q = i * 32 + ty;
        float l = l_sm[q];
        int sidx = qt * 128 + q;
        size_t base = ((size_t)(b * NS + sidx) * NH + h) * NHD;
        float av[8];
        #pragma unroll
        for (int cp = 0; cp < 4; cp++) unpackf2(acc2[i][cp], av[2*cp], av[2*cp+1]);
        #pragma unroll
        for (int c = 0; c < 8; c++) g_ctx[base + tx * 8 + c] = __fdiv_rn(av[c], l);
        g_ctx[base + 64 + tx] = __fdiv_rn(acc8[i], l);
    }
}

// ---------------- 8) head mix (o_mat, comp fp32, 3-way ILP) + 8-bit quant ---------
__global__ void ctxmix_kernel(const float* __restrict__ om) {
    int t = blockIdx.x, tid = threadIdx.x;
    __shared__ float C[ND], Y[ND], O[NH*NH], red[128];
    for (int c = tid; c < NH*NH; c += 128) O[c] = om[c];
    for (int c = tid; c < ND; c += 128) C[c] = g_ctx[(size_t)t * ND + c];
    __syncthreads();
    #pragma unroll
    for (int ob = 0; ob < 3; ob++) {
        int o0 = tid + ob * 384, o1 = o0 + 128, o2 = o0 + 256;
        int h0 = o0 / NHD, d0 = o0 - h0 * NHD;
        int h1 = o1 / NHD, d1 = o1 - h1 * NHD;
        int h2 = o2 / NHD, d2 = o2 - h2 * NHD;
        float s0 = 0.f, c0 = 0.f, s1 = 0.f, c1 = 0.f, s2 = 0.f, c2 = 0.f;
        #pragma unroll
        for (int g = 0; g < NH; g++) {
            df_mac(O[g * NH + h0], C[g * NHD + d0], s0, c0);
            df_mac(O[g * NH + h1], C[g * NHD + d1], s1, c1);
            df_mac(O[g * NH + h2], C[g * NHD + d2], s2, c2);
        }
        Y[o0] = s0 + c0; Y[o1] = s1 + c1; Y[o2] = s2 + c2;
    }
    __syncthreads();
    float mx = block_max_abs_128(Y, ND, tid, red);
    float s = fmaxf(__fdiv_rn(mx, 127.0f), 1e-8f);
    if (tid == 0) g_cs[t] = s;
    for (int w = tid; w < KW; w += 128)
        g_cq[(size_t)t * KW + w] = pack4q(Y[4*w], Y[4*w+1], Y[4*w+2], Y[4*w+3], s, -128.f, 127.f);
}

// ---------------- launch ----------------
extern "C" void kernel_launch(void* const* d_in, const int* in_sizes, int n_in,
                              void* d_out, int out_size) {
    const float* hs  = (const float*)d_in[0];
    const float* Wq  = (const float*)d_in[1];
    const float* bq  = (const float*)d_in[2];
    const float* Wk  = (const float*)d_in[3];
    const float* bk  = (const float*)d_in[4];
    const float* Wv  = (const float*)d_in[5];
    const float* bv  = (const float*)d_in[6];
    const float* Wo  = (const float*)d_in[7];
    const float* bo  = (const float*)d_in[8];
    const float* lnA = (const float*)d_in[9];
    const float* lnB = (const float*)d_in[10];
    const float* ldg = (const float*)d_in[11];
    const float* vc  = (const float*)d_in[12];
    const float* om  = (const float*)d_in[13];
    float* out = (float*)d_out;

    inv_kernel<<<4, 128>>>(lnA, lnB, vc, om);                         // 1
    wtrans_qkv_kernel<<<dim3(ND, 3), 128>>>(Wq, bq, Wk, bk, Wv, ldg); // 2
    wtrans_vmix_kernel<<<ND, 128>>>(vc, bv);                          // 3
    act_kernel<<<NT, 128>>>(hs, ldg, lnA, lnB);                       // 4
    gemm_dp4a_kernel<<<dim3(27, 64), 256>>>(0, nullptr, nullptr);     // 5

    const int ATT_SMEM = (128 * QSTR + 64 * QSTR * 2 + 128 * PSTR + 384) * 4;  // 111.5 KB
    cudaFuncSetAttribute(attn_kernel, cudaFuncAttributeMaxDynamicSharedMemorySize, ATT_SMEM);
    attn_kernel<<<dim3(8, NB * NH), 256, ATT_SMEM>>>();               // 6

    wtrans_o_kernel<<<ND, 128>>>(Wo);                                 // 7
    ctxmix_kernel<<<NT, 128>>>(om);                                   // 8
    gemm_dp4a_kernel<<<dim3(9, 64), 256>>>(1, bo, out);               // 9
}

// round 14
// speedup vs baseline: 1.0007x; 1.0007x over previous
#include <cuda_runtime.h>
#include <math.h>

// ---------------- problem constants ----------------
#define NB 8
#define NS 1024
#define ND 1152
#define NH 16
#define NHD 72
#define NL 32
#define NR 36
#define NT (NB*NS)          // 8192 tokens
#define KW (ND/4)           // 288 packed int32 words per row
#define BHS (NS*NHD)        // 73728 floats per (b,h) of q/k/v
#define QSTR 76             // Q/K/V smem row stride (conflict-free, 16B-aligned)
#define PSTR 68             // Ps row stride: 16B-aligned rows -> float4 phase-B reads

typedef unsigned long long ull;

// ---------------- device scratch (static; no allocations) ----------------
__device__ __align__(16) float  g_invA[NL*NL];
__device__ __align__(16) float  g_invB[NR*NR];
__device__ __align__(16) float  g_invVC[NHD*NHD];
__device__ __align__(16) float  g_invO[NH*NH];
__device__ double g_gj[4][72*144];

__device__ __align__(16) int    g_wq[3456*KW];
__device__ __align__(16) float  g_ws[3456];
__device__ __align__(16) float  g_bias[3456];
__device__ __align__(16) float  g_WvT[ND*ND];
__device__ __align__(16) int    g_woq[ND*KW];
__device__ __align__(16) float  g_wos[ND];

__device__ __align__(16) int    g_xq[NT*KW];
__device__ __align__(16) float  g_xs[NT];
__device__ __align__(16) float  g_q[NT*ND];        // (B,H,S,HD)
__device__ __align__(16) float  g_k[NT*ND];
__device__ __align__(16) float  g_v[NT*ND];
__device__ __align__(16) float  g_ctx[NT*ND];      // (B,S,H,HD)
__device__ __align__(16) int    g_cq[NT*KW];
__device__ __align__(16) float  g_cs[NT];

// ---------------- f32x2 packed primitives (sm_103a) ----------------
__device__ __forceinline__ ull packf2(float lo, float hi) {
    ull r; asm("mov.b64 %0, {%1, %2};" : "=l"(r) : "f"(lo), "f"(hi)); return r;
}
__device__ __forceinline__ void unpackf2(ull v, float& lo, float& hi) {
    asm("mov.b64 {%0, %1}, %2;" : "=f"(lo), "=f"(hi) : "l"(v));
}
__device__ __forceinline__ void fma2(ull& d, ull a, ull b) {
    asm("fma.rn.f32x2 %0, %1, %2, %3;" : "=l"(d) : "l"(a), "l"(b), "l"(d));
}
__device__ __forceinline__ void mul2(ull& d, ull a) {
    asm("mul.rn.f32x2 %0, %1, %2;" : "=l"(d) : "l"(d), "l"(a));
}

// ---------------- compensated fp32 (double-float) primitives ----------------
__device__ __forceinline__ void df_mac(float a, float b, float& s, float& c) {
    float p = a * b;
    float e = fmaf(a, b, -p);
    float t = s + p;
    float bb = t - s;
    float err = (s - (t - bb)) + (p - bb);
    s = t;
    c += err + e;
}
__device__ __forceinline__ void df_mac2(float ahi, float alo, float b, float& s, float& c) {
    float p = ahi * b;
    float e = fmaf(ahi, b, -p);
    e = fmaf(alo, b, e);
    float t = s + p;
    float bb = t - s;
    float err = (s - (t - bb)) + (p - bb);
    s = t;
    c += err + e;
}
__device__ __forceinline__ float df_dequant(float a, float sx, float sw, float bias) {
    float p1 = a * sx;  float e1 = fmaf(a, sx, -p1);
    float p2 = p1 * sw; float e2 = fmaf(p1, sw, -p2);
    e2 = fmaf(e1, sw, e2);
    float t = p2 + bias;
    float bb = t - p2;
    float err = (p2 - (t - bb)) + (bias - bb);
    return t + (err + e2);
}

// ---------------- helpers ----------------
__device__ __forceinline__ int pack4q(float a, float b, float c, float d,
                                      float s, float lo, float hi) {
    int ia = (int)fminf(fmaxf(rintf(__fdiv_rn(a, s)), lo), hi);
    int ib = (int)fminf(fmaxf(rintf(__fdiv_rn(b, s)), lo), hi);
    int ic = (int)fminf(fmaxf(rintf(__fdiv_rn(c, s)), lo), hi);
    int id = (int)fminf(fmaxf(rintf(__fdiv_rn(d, s)), lo), hi);
    return (ia & 0xFF) | ((ib & 0xFF) << 8) | ((ic & 0xFF) << 16) | ((id & 0xFF) << 24);
}

__device__ __forceinline__ float block_max_abs_128(const float* Y, int n, int tid, float* red) {
    float mx = 0.f;
    for (int c = tid; c < n; c += 128) mx = fmaxf(mx, fabsf(Y[c]));
    red[tid] = mx;
    __syncthreads();
    for (int o = 64; o > 0; o >>= 1) {
        if (tid < o) red[tid] = fmaxf(red[tid], red[tid + o]);
        __syncthreads();
    }
    float r = red[0];
    __syncthreads();
    return r;
}

// accurate expf (Cody-Waite + deg-6 Taylor) on the FMA pipe, fast-math-immune
__device__ __forceinline__ float exp_acc(float x) {
    if (x < -87.0f) return 0.0f;
    float n = rintf(x * 1.4426950408889634f);
    float r = fmaf(-n, 0.6931471824645996f, x);
    r = fmaf(n, 1.9046542999577600e-9f, r);
    float p = 1.3888888888888889e-3f;
    p = fmaf(p, r, 8.3333333333333333e-3f);
    p = fmaf(p, r, 4.1666666666666664e-2f);
    p = fmaf(p, r, 1.6666666666666666e-1f);
    p = fmaf(p, r, 0.5f);
    p = fmaf(p, r, 1.0f);
    p = fmaf(p, r, 1.0f);
    int ni = (int)n;
    return p * __int_as_float((ni + 127) << 23);
}

// ---------------- 1) small-matrix inverses (fp64 Gauss-Jordan, tiny) ---------
__global__ void inv_kernel(const float* __restrict__ Asrc, const float* __restrict__ Bsrc,
                           const float* __restrict__ Vsrc, const float* __restrict__ Osrc) {
    int blk = blockIdx.x, tid = threadIdx.x;
    int n; const float* src; float* dst;
    if      (blk == 0) { n = NL;  src = Asrc; dst = g_invA;  }
    else if (blk == 1) { n = NR;  src = Bsrc; dst = g_invB;  }
    else if (blk == 2) { n = NHD; src = Vsrc; dst = g_invVC; }
    else               { n = NH;  src = Osrc; dst = g_invO;  }
    double* aug = g_gj[blk];
    int n2 = 2 * n;
    for (int idx = tid; idx < n * n2; idx += blockDim.x) {
        int i = idx / n2, j = idx - i * n2;
        aug[idx] = (j < n) ? (double)src[i * n + j] : ((j - n) == i ? 1.0 : 0.0);
    }
    __syncthreads();
    __shared__ int piv;
    for (int k = 0; k < n; k++) {
        if (tid == 0) {
            int p = k; double best = fabs(aug[k * n2 + k]);
            for (int i = k + 1; i < n; i++) {
                double v = fabs(aug[i * n2 + k]);
                if (v > best) { best = v; p = i; }
            }
            piv = p;
        }
        __syncthreads();
        if (piv != k) {
            for (int j = tid; j < n2; j += blockDim.x) {
                double t = aug[k * n2 + j];
                aug[k * n2 + j] = aug[piv * n2 + j];
                aug[piv * n2 + j] = t;
            }
        }
        __syncthreads();
        double pv = aug[k * n2 + k];
        __syncthreads();
        for (int j = tid; j < n2; j += blockDim.x) aug[k * n2 + j] /= pv;
        __syncthreads();
        for (int i = tid; i < n; i += blockDim.x) {
            if (i == k) continue;
            double f = aug[i * n2 + k];
            for (int j = 0; j < n2; j++) aug[i * n2 + j] -= f * aug[k * n2 + j];
        }
        __syncthreads();
    }
    for (int idx = tid; idx < n * n; idx += blockDim.x)
        dst[idx] = (float)aug[(idx / n) * n2 + n + (idx % n)];
}

// ---------------- 2) q/k/v weight kron transform (comp fp32, 3-way ILP) -----------
__global__ void wtrans_qkv_kernel(const float* __restrict__ Wq_, const float* __restrict__ bq_,
                                  const float* __restrict__ Wk_, const float* __restrict__ bk_,
                                  const float* __restrict__ Wv_, const float* __restrict__ ldg) {
    int which = blockIdx.y, i = blockIdx.x, tid = threadIdx.x;
    const float* W = (which == 0) ? Wq_ : (which == 1) ? Wk_ : Wv_;
    __shared__ float X[ND], Yf[ND];
    __shared__ float2 T1[ND];
    __shared__ float iA[NL*NL], iB[NR*NR], red[128];
    for (int c = tid; c < NL*NL; c += 128) iA[c] = g_invA[c];
    for (int c = tid; c < NR*NR; c += 128) iB[c] = g_invB[c];
    for (int c = tid; c < ND; c += 128) X[c] = W[(size_t)i * ND + c] * __frcp_rn(ldg[c]);
    __syncthreads();
    #pragma unroll
    for (int ob = 0; ob < 3; ob++) {
        int o0 = tid + ob * 384, o1 = o0 + 128, o2 = o0 + 256;
        int p0 = o0 / NR, r0 = o0 - p0 * NR;
        int p1 = o1 / NR, r1 = o1 - p1 * NR;
        int p2 = o2 / NR, r2 = o2 - p2 * NR;
        float s0 = 0.f, c0 = 0.f, s1 = 0.f, c1 = 0.f, s2 = 0.f, c2 = 0.f;
        #pragma unroll 8
        for (int l = 0; l < NL; l++) {
            df_mac(iA[p0 * NL + l], X[l * NR + r0], s0, c0);
            df_mac(iA[p1 * NL + l], X[l * NR + r1], s1, c1);
            df_mac(iA[p2 * NL + l], X[l * NR + r2], s2, c2);
        }
        T1[o0] = make_float2(s0, c0);
        T1[o1] = make_float2(s1, c1);
        T1[o2] = make_float2(s2, c2);
    }
    __syncthreads();
    #pragma unroll
    for (int ob = 0; ob < 3; ob++) {
        int o0 = tid + ob * 384, o1 = o0 + 128, o2 = o0 + 256;
        int p0 = o0 / NR, q0 = o0 - p0 * NR;
        int p1 = o1 / NR, q1 = o1 - p1 * NR;
        int p2 = o2 / NR, q2 = o2 - p2 * NR;
        float s0 = 0.f, c0 = 0.f, s1 = 0.f, c1 = 0.f, s2 = 0.f, c2 = 0.f;
        #pragma unroll 6
        for (int r = 0; r < NR; r++) {
            float2 t0 = T1[p0 * NR + r]; df_mac2(t0.x, t0.y, iB[q0 * NR + r], s0, c0);
            float2 t1 = T1[p1 * NR + r]; df_mac2(t1.x, t1.y, iB[q1 * NR + r], s1, c1);
            float2 t2 = T1[p2 * NR + r]; df_mac2(t2.x, t2.y, iB[q2 * NR + r], s2, c2);
        }
        Yf[o0] = s0 + c0; Yf[o1] = s1 + c1; Yf[o2] = s2 + c2;
    }
    __syncthreads();
    if (which == 2) {
        for (int c = tid; c < ND; c += 128) g_WvT[(size_t)i * ND + c] = Yf[c];
        return;
    }
    float mx = block_max_abs_128(Yf, ND, tid, red);
    float s = fmaxf(__fdiv_rn(mx, 7.0f), 1e-8f);
    int row = which * ND + i;
    for (int w = tid; w < KW; w += 128)
        g_wq[(size_t)row * KW + w] = pack4q(Yf[4*w], Yf[4*w+1], Yf[4*w+2], Yf[4*w+3], s, -8.f, 7.f);
    if (tid == 0) {
        g_ws[row] = s;
        g_bias[row] = (which == 0 ? bq_ : bk_)[i];
    }
}

// ---------------- 3) v weight: vc output-channel mix (9-way ILP) ----------
__global__ void wtrans_vmix_kernel(const float* __restrict__ vc, const float* __restrict__ bv) {
    int rr = blockIdx.x, tid = threadIdx.x;
    int h = rr / NHD, e = rr - h * NHD;
    __shared__ float Y[ND], red[128], vcol[NHD];
    for (int d = tid; d < NHD; d += 128) vcol[d] = vc[d * NHD + e];
    __syncthreads();
    float ys[9], yc[9];
    #pragma unroll
    for (int jj = 0; jj < 9; jj++) { ys[jj] = 0.f; yc[jj] = 0.f; }
    for (int d = 0; d < NHD; d++) {
        float vv = vcol[d];
        const float* row = &g_WvT[(size_t)(h * NHD + d) * ND];
        #pragma unroll
        for (int jj = 0; jj < 9; jj++) df_mac(row[tid + jj * 128], vv, ys[jj], yc[jj]);
    }
    #pragma unroll
    for (int jj = 0; jj < 9; jj++) Y[tid + jj * 128] = ys[jj] + yc[jj];
    __syncthreads();
    float mx = block_max_abs_128(Y, ND, tid, red);
    float s = fmaxf(__fdiv_rn(mx, 7.0f), 1e-8f);
    int row = 2 * ND + rr;
    for (int w = tid; w < KW; w += 128)
        g_wq[(size_t)row * KW + w] = pack4q(Y[4*w], Y[4*w+1], Y[4*w+2], Y[4*w+3], s, -8.f, 7.f);
    if (tid == 0) {
        g_ws[row] = s;
        double bt = 0.0;
        for (int d = 0; d < NHD; d++) bt += (double)bv[h * NHD + d] * (double)vcol[d];
        g_bias[row] = (float)bt;
    }
}

// ---------------- 4) output weight transform (comp fp32, 3-way ILP) ---------------
__global__ void wtrans_o_kernel(const float* __restrict__ Wo_) {
    int o = blockIdx.x, tid = threadIdx.x;
    __shared__ float M[ND], Yf[ND], red[128];
    __shared__ float2 T[NH*NHD];
    __shared__ float iV[NHD*NHD], iO[NH*NH];
    for (int c = tid; c < NHD*NHD; c += 128) iV[c] = g_invVC[c];
    for (int c = tid; c < NH*NH; c += 128) iO[c] = g_invO[c];
    for (int c = tid; c < ND; c += 128) M[c] = Wo_[(size_t)o * ND + c];
    __syncthreads();
    #pragma unroll
    for (int ob = 0; ob < 3; ob++) {
        int i0 = tid + ob * 384, i1 = i0 + 128, i2 = i0 + 256;
        int g0 = i0 / NHD, e0 = i0 - g0 * NHD;
        int g1 = i1 / NHD, e1 = i1 - g1 * NHD;
        int g2 = i2 / NHD, e2 = i2 - g2 * NHD;
        float s0 = 0.f, c0 = 0.f, s1 = 0.f, c1 = 0.f, s2 = 0.f, c2 = 0.f;
        #pragma unroll 8
        for (int d = 0; d < NHD; d++) {
            df_mac(M[g0 * NHD + d], iV[e0 * NHD + d], s0, c0);
            df_mac(M[g1 * NHD + d], iV[e1 * NHD + d], s1, c1);
            df_mac(M[g2 * NHD + d], iV[e2 * NHD + d], s2, c2);
        }
        T[i0] = make_float2(s0, c0);
        T[i1] = make_float2(s1, c1);
        T[i2] = make_float2(s2, c2);
    }
    __syncthreads();
    #pragma unroll
    for (int ob = 0; ob < 3; ob++) {
        int i0 = tid + ob * 384, i1 = i0 + 128, i2 = i0 + 256;
        int h0 = i0 / NHD, e0 = i0 - h0 * NHD;
        int h1 = i1 / NHD, e1 = i1 - h1 * NHD;
        int h2 = i2 / NHD, e2 = i2 - h2 * NHD;
        float s0 = 0.f, c0 = 0.f, s1 = 0.f, c1 = 0.f, s2 = 0.f, c2 = 0.f;
        #pragma unroll
        for (int g = 0; g < NH; g++) {
            float2 t0 = T[g * NHD + e0]; df_mac2(t0.x, t0.y, iO[h0 * NH + g], s0, c0);
            float2 t1 = T[g * NHD + e1]; df_mac2(t1.x, t1.y, iO[h1 * NH + g], s1, c1);
            float2 t2 = T[g * NHD + e2]; df_mac2(t2.x, t2.y, iO[h2 * NH + g], s2, c2);
        }
        Yf[i0] = s0 + c0; Yf[i1] = s1 + c1; Yf[i2] = s2 + c2;
    }
    __syncthreads();
    float mx = block_max_abs_128(Yf, ND, tid, red);
    float s = fmaxf(__fdiv_rn(mx, 7.0f), 1e-8f);
    for (int w = tid; w < KW; w += 128)
        g_woq[(size_t)o * KW + w] = pack4q(Yf[4*w], Yf[4*w+1], Yf[4*w+2], Yf[4*w+3], s, -8.f, 7.f);
    if (tid == 0) g_wos[o] = s;
}

// ---------------- 5) activation kron transform (comp fp32, 3-way ILP) + quant -----
__global__ void act_kernel(const float* __restrict__ hs, const float* __restrict__ ldg,
                           const float* __restrict__ lnA, const float* __restrict__ lnB) {
    int t = blockIdx.x, tid = threadIdx.x;
    __shared__ float X[ND], Yf[ND];
    __shared__ float2 T1[ND];
    __shared__ float A[NL*NL], Bm[NR*NR], red[128];
    for (int c = tid; c < NL*NL; c += 128) A[c] = lnA[c];
    for (int c = tid; c < NR*NR; c += 128) Bm[c] = lnB[c];
    for (int c = tid; c < ND; c += 128) X[c] = hs[(size_t)t * ND + c] * ldg[c];
    __syncthreads();
    #pragma unroll
    for (int ob = 0; ob < 3; ob++) {
        int o0 = tid + ob * 384, o1 = o0 + 128, o2 = o0 + 256;
        int p0 = o0 / NR, r0 = o0 - p0 * NR;
        int p1 = o1 / NR, r1 = o1 - p1 * NR;
        int p2 = o2 / NR, r2 = o2 - p2 * NR;
        float s0 = 0.f, c0 = 0.f, s1 = 0.f, c1 = 0.f, s2 = 0.f, c2 = 0.f;
        #pragma unroll 8
        for (int l = 0; l < NL; l++) {
            df_mac(A[l * NL + p0], X[l * NR + r0], s0, c0);
            df_mac(A[l * NL + p1], X[l * NR + r1], s1, c1);
            df_mac(A[l * NL + p2], X[l * NR + r2], s2, c2);
        }
        T1[o0] = make_float2(s0, c0);
        T1[o1] = make_float2(s1, c1);
        T1[o2] = make_float2(s2, c2);
    }
    __syncthreads();
    #pragma unroll
    for (int ob = 0; ob < 3; ob++) {
        int o0 = tid + ob * 384, o1 = o0 + 128, o2 = o0 + 256;
        int p0 = o0 / NR, q0 = o0 - p0 * NR;
        int p1 = o1 / NR, q1 = o1 - p1 * NR;
        int p2 = o2 / NR, q2 = o2 - p2 * NR;
        float s0 = 0.f, c0 = 0.f, s1 = 0.f, c1 = 0.f, s2 = 0.f, c2 = 0.f;
        #pragma unroll 6
        for (int r = 0; r < NR; r++) {
            float2 t0 = T1[p0 * NR + r]; df_mac2(t0.x, t0.y, Bm[r * NR + q0], s0, c0);
            float2 t1 = T1[p1 * NR + r]; df_mac2(t1.x, t1.y, Bm[r * NR + q1], s1, c1);
            float2 t2 = T1[p2 * NR + r]; df_mac2(t2.x, t2.y, Bm[r * NR + q2], s2, c2);
        }
        Yf[o0] = s0 + c0; Yf[o1] = s1 + c1; Yf[o2] = s2 + c2;
    }
    __syncthreads();
    float mx = block_max_abs_128(Yf, ND, tid, red);
    float s = fmaxf(__fdiv_rn(mx, 127.0f), 1e-8f);
    if (tid == 0) g_xs[t] = s;
    for (int w = tid; w < KW; w += 128)
        g_xq[(size_t)t * KW + w] = pack4q(Yf[4*w], Yf[4*w+1], Yf[4*w+2], Yf[4*w+3], s, -128.f, 127.f);
}

// ---------------- 6) dp4a GEMM (mode 0: qkv projections+scatter; mode 1: final) ----
__global__ __launch_bounds__(256) void gemm_dp4a_kernel(int mode, const float* __restrict__ bias_ext,
                                                        float* __restrict__ outp) {
    __shared__ int Xs[16][128];
    __shared__ int Wsm[16][128];
    const int*   __restrict__ Xq  = mode ? g_cq  : g_xq;
    const float* __restrict__ xs  = mode ? g_cs  : g_xs;
    const int*   __restrict__ Wp  = mode ? g_woq : g_wq;
    const float* __restrict__ wsp = mode ? g_wos : g_ws;
    int m0 = blockIdx.y * 128, n0 = blockIdx.x * 128;
    int tid = threadIdx.x;
    int acc[8][8];
    #pragma unroll
    for (int i = 0; i < 8; i++)
        #pragma unroll
        for (int j = 0; j < 8; j++) acc[i][j] = 0;
    int r = tid >> 2, wg = (tid & 3) << 2;
    int ty = tid >> 4, tx = tid & 15;
    for (int kt = 0; kt < 18; kt++) {
        #pragma unroll
        for (int half = 0; half < 2; half++) {
            int row = r + (half << 6);
            int4 xv = *(const int4*)&Xq[(size_t)(m0 + row) * KW + kt * 16 + wg];
            Xs[wg + 0][row] = xv.x; Xs[wg + 1][row] = xv.y;
            Xs[wg + 2][row] = xv.z; Xs[wg + 3][row] = xv.w;
            int4 wv = *(const int4*)&Wp[(size_t)(n0 + row) * KW + kt * 16 + wg];
            Wsm[wg + 0][row] = wv.x; Wsm[wg + 1][row] = wv.y;
            Wsm[wg + 2][row] = wv.z; Wsm[wg + 3][row] = wv.w;
        }
        __syncthreads();
        #pragma unroll 4
        for (int kk = 0; kk < 16; kk++) {
            int4 xa = *(const int4*)&Xs[kk][ty << 3];
            int4 xb = *(const int4*)&Xs[kk][(ty << 3) + 4];
            int4 wa = *(const int4*)&Wsm[kk][tx << 3];
            int4 wb = *(const int4*)&Wsm[kk][(tx << 3) + 4];
            int xv[8] = {xa.x, xa.y, xa.z, xa.w, xb.x, xb.y, xb.z, xb.w};
            int wv[8] = {wa.x, wa.y, wa.z, wa.w, wb.x, wb.y, wb.z, wb.w};
            #pragma unroll
            for (int i = 0; i < 8; i++)
                #pragma unroll
                for (int j = 0; j < 8; j++)
                    acc[i][j] = __dp4a(xv[i], wv[j], acc[i][j]);
        }
        __syncthreads();
    }
    #pragma unroll
    for (int i = 0; i < 8; i++) {
        int m = m0 + (ty << 3) + i;
        float sx = xs[m];
        #pragma unroll
        for (int j = 0; j < 8; j++) {
            int n = n0 + (tx << 3) + j;
            if (mode) {
                float val = df_dequant((float)acc[i][j], sx, wsp[n], bias_ext[n]);
                outp[(size_t)m * ND + n] = val;
            } else {
                float val = df_dequant((float)acc[i][j], sx, wsp[n], g_bias[n]);
                int which = n / ND;
                int jj = n - which * ND;
                int h = jj / NHD, hd = jj - h * NHD;
                int b = m >> 10, sidx = m & 1023;
                float* dst = (which == 0) ? g_q : (which == 1) ? g_k : g_v;
                dst[((size_t)((b << 4) + h) * NS + sidx) * NHD + hd] = val;
            }
        }
    }
}

// ---------------- 7) attention: q128 (best base), phase-B Ps via float4 ----------------
// ty = tid>>3 (0..31), tx = tid&7. q rows: i*32+ty (i 0..3), k cols: j*8+tx.
// Identical per-value arithmetic order to R8 -> bit-identical output.
__global__ __launch_bounds__(256, 2) void attn_kernel() {
    extern __shared__ float sm[];
    float* Qs   = sm;                       // 128*76
    float* Ks   = sm + 128 * QSTR;          //  64*76
    float* Vs   = Ks + 64 * QSTR;           //  64*76
    float* Ps   = Vs + 64 * QSTR;           // 128*68
    float* m_sm = Ps + 128 * PSTR;
    float* l_sm = m_sm + 128;
    float* f_sm = l_sm + 128;
    int bh = blockIdx.y, qt = blockIdx.x, tid = threadIdx.x;
    const float* Qp = g_q + (size_t)bh * BHS + (size_t)qt * 128 * NHD;
    const float* Kp = g_k + (size_t)bh * BHS;
    const float* Vp = g_v + (size_t)bh * BHS;
    for (int idx = tid; idx < 128 * 18; idx += 256) {
        int row = idx / 18, c = idx - row * 18;
        ((float4*)(Qs + row * QSTR))[c] = ((const float4*)(Qp + row * NHD))[c];
    }
    if (tid < 128) { m_sm[tid] = -1e30f; l_sm[tid] = 0.f; }
    ull acc2[4][4];
    float acc8[4];
    #pragma unroll
    for (int i = 0; i < 4; i++) {
        #pragma unroll
        for (int cp = 0; cp < 4; cp++) acc2[i][cp] = 0ull;
        acc8[i] = 0.f;
    }
    int ty = tid >> 3, tx = tid & 7;
    __syncthreads();

    for (int kt0 = 0; kt0 < NS; kt0 += 64) {
        for (int idx = tid; idx < 64 * 18; idx += 256) {
            int row = idx / 18, c = idx - row * 18;
            ((float4*)(Ks + row * QSTR))[c] = ((const float4*)(Kp + (kt0 + row) * NHD))[c];
            ((float4*)(Vs + row * QSTR))[c] = ((const float4*)(Vp + (kt0 + row) * NHD))[c];
        }
        __syncthreads();
        // ---- phase A: two passes of 4 j, accumulators paired along d ----
        #pragma unroll
        for (int pass = 0; pass < 2; pass++) {
            ull sacc[4][4];
            #pragma unroll
            for (int i = 0; i < 4; i++)
                #pragma unroll
                for (int jj = 0; jj < 4; jj++) sacc[i][jj] = 0ull;
            #pragma unroll 3
            for (int d4 = 0; d4 < 18; d4++) {
                longlong2 qv[4], kv[4];
                #pragma unroll
                for (int i = 0; i < 4; i++)
                    qv[i] = *(const longlong2*)&Qs[(i * 32 + ty) * QSTR + d4 * 4];
                #pragma unroll
                for (int jj = 0; jj < 4; jj++)
                    kv[jj] = *(const longlong2*)&Ks[((pass * 4 + jj) * 8 + tx) * QSTR + d4 * 4];
                #pragma unroll
                for (int i = 0; i < 4; i++)
                    #pragma unroll
                    for (int jj = 0; jj < 4; jj++) {
                        fma2(sacc[i][jj], (ull)qv[i].x, (ull)kv[jj].x);
                        fma2(sacc[i][jj], (ull)qv[i].y, (ull)kv[jj].y);
                    }
            }
            #pragma unroll
            for (int i = 0; i < 4; i++)
                #pragma unroll
                for (int jj = 0; jj < 4; jj++) {
                    float lo, hi;
                    unpackf2(sacc[i][jj], lo, hi);
                    Ps[(i * 32 + ty) * PSTR + (pass * 4 + jj) * 8 + tx] = lo + hi;
                }
        }
        // ---- online softmax ----
        #pragma unroll
        for (int i = 0; i < 4; i++) {
            int q = i * 32 + ty;
            float s[8];
            #pragma unroll
            for (int j = 0; j < 8; j++) s[j] = Ps[q * PSTR + j * 8 + tx];
            float rm = s[0];
            #pragma unroll
            for (int j = 1; j < 8; j++) rm = fmaxf(rm, s[j]);
            rm = fmaxf(rm, __shfl_xor_sync(0xffffffffu, rm, 1, 8));
            rm = fmaxf(rm, __shfl_xor_sync(0xffffffffu, rm, 2, 8));
            rm = fmaxf(rm, __shfl_xor_sync(0xffffffffu, rm, 4, 8));
            float mo = m_sm[q];
            float mn = fmaxf(mo, rm);
            float rs = 0.f;
            #pragma unroll
            for (int j = 0; j < 8; j++) {
                float p = exp_acc(s[j] - mn);
                Ps[q * PSTR + j * 8 + tx] = p;
                rs += p;
            }
            rs += __shfl_xor_sync(0xffffffffu, rs, 1, 8);
            rs += __shfl_xor_sync(0xffffffffu, rs, 2, 8);
            rs += __shfl_xor_sync(0xffffffffu, rs, 4, 8);
            if (tx == 0) {
                float f = exp_acc(mo - mn);
                f_sm[q] = f;
                l_sm[q] = l_sm[q] * f + rs;
                m_sm[q] = mn;
            }
        }
        __syncthreads();
        // ---- phase B: acc = acc*f + P @ V (Ps read via float4) ----
        #pragma unroll
        for (int i = 0; i < 4; i++) {
            float f = f_sm[i * 32 + ty];
            ull f2 = packf2(f, f);
            #pragma unroll
            for (int cp = 0; cp < 4; cp++) mul2(acc2[i][cp], f2);
            acc8[i] *= f;
        }
        for (int k4 = 0; k4 < 16; k4++) {
            float4 pq[4];
            #pragma unroll
            for (int i = 0; i < 4; i++)
                pq[i] = *(const float4*)&Ps[(i * 32 + ty) * PSTR + k4 * 4];
            #pragma unroll
            for (int kk = 0; kk < 4; kk++) {
                int k = k4 * 4 + kk;
                longlong2 va = *(const longlong2*)&Vs[k * QSTR + tx * 8];
                longlong2 vb = *(const longlong2*)&Vs[k * QSTR + tx * 8 + 4];
                float v8 = Vs[k * QSTR + 64 + tx];
                #pragma unroll
                for (int i = 0; i < 4; i++) {
                    float p = ((const float*)&pq[i])[kk];
                    ull p2 = packf2(p, p);
                    fma2(acc2[i][0], p2, (ull)va.x);
                    fma2(acc2[i][1], p2, (ull)va.y);
                    fma2(acc2[i][2], p2, (ull)vb.x);
                    fma2(acc2[i][3], p2, (ull)vb.y);
                    acc8[i] = fmaf(p, v8, acc8[i]);
                }
            }
        }
        __syncthreads();
    }
    // ---- write ctx (B,S,H,HD): c = tx*8 + 0..7 and 64+tx ----
    int h = bh & 15, b = bh >> 4;
    #pragma unroll
    for (int i = 0; i < 4; i++) {
        int q = i * 32 + ty;
        float l = l_sm[q];
        int sidx = qt * 128 + q;
        size_t base = ((size_t)(b * NS + sidx) * NH + h) * NHD;
        float av[8];
        #pragma unroll
        for (int cp = 0; cp < 4; cp++) unpackf2(acc2[i][cp], av[2*cp], av[2*cp+1]);
        #pragma unroll
        for (int c = 0; c < 8; c++) g_ctx[base + tx * 8 + c] = __fdiv_rn(av[c], l);
        g_ctx[base + 64 + tx] = __fdiv_rn(acc8[i], l);
    }
}

// ---------------- 8) head mix (o_mat, comp fp32, 3-way ILP) + 8-bit quant ---------
__global__ void ctxmix_kernel(const float* __restrict__ om) {
    int t = blockIdx.x, tid = threadIdx.x;
    __shared__ float C[ND], Y[ND], O[NH*NH], red[128];
    for (int c = tid; c < NH*NH; c += 128) O[c] = om[c];
    for (int c = tid; c < ND; c += 128) C[c] = g_ctx[(size_t)t * ND + c];
    __syncthreads();
    #pragma unroll
    for (int ob = 0; ob < 3; ob++) {
        int o0 = tid + ob * 384, o1 = o0 + 128, o2 = o0 + 256;
        int h0 = o0 / NHD, d0 = o0 - h0 * NHD;
        int h1 = o1 / NHD, d1 = o1 - h1 * NHD;
        int h2 = o2 / NHD, d2 = o2 - h2 * NHD;
        float s0 = 0.f, c0 = 0.f, s1 = 0.f, c1 = 0.f, s2 = 0.f, c2 = 0.f;
        #pragma unroll
        for (int g = 0; g < NH; g++) {
            df_mac(O[g * NH + h0], C[g * NHD + d0], s0, c0);
            df_mac(O[g * NH + h1], C[g * NHD + d1], s1, c1);
            df_mac(O[g * NH + h2], C[g * NHD + d2], s2, c2);
        }
        Y[o0] = s0 + c0; Y[o1] = s1 + c1; Y[o2] = s2 + c2;
    }
    __syncthreads();
    float mx = block_max_abs_128(Y, ND, tid, red);
    float s = fmaxf(__fdiv_rn(mx, 127.0f), 1e-8f);
    if (tid == 0) g_cs[t] = s;
    for (int w = tid; w < KW; w += 128)
        g_cq[(size_t)t * KW + w] = pack4q(Y[4*w], Y[4*w+1], Y[4*w+2], Y[4*w+3], s, -128.f, 127.f);
}

// ---------------- launch ----------------
extern "C" void kernel_launch(void* const* d_in, const int* in_sizes, int n_in,
                              void* d_out, int out_size) {
    const float* hs  = (const float*)d_in[0];
    const float* Wq  = (const float*)d_in[1];
    const float* bq  = (const float*)d_in[2];
    const float* Wk  = (const float*)d_in[3];
    const float* bk  = (const float*)d_in[4];
    const float* Wv  = (const float*)d_in[5];
    const float* bv  = (const float*)d_in[6];
    const float* Wo  = (const float*)d_in[7];
    const float* bo  = (const float*)d_in[8];
    const float* lnA = (const float*)d_in[9];
    const float* lnB = (const float*)d_in[10];
    const float* ldg = (const float*)d_in[11];
    const float* vc  = (const float*)d_in[12];
    const float* om  = (const float*)d_in[13];
    float* out = (float*)d_out;

    inv_kernel<<<4, 128>>>(lnA, lnB, vc, om);                         // 1
    wtrans_qkv_kernel<<<dim3(ND, 3), 128>>>(Wq, bq, Wk, bk, Wv, ldg); // 2
    wtrans_vmix_kernel<<<ND, 128>>>(vc, bv);                          // 3
    act_kernel<<<NT, 128>>>(hs, ldg, lnA, lnB);                       // 4
    gemm_dp4a_kernel<<<dim3(27, 64), 256>>>(0, nullptr, nullptr);     // 5

    const int ATT_SMEM = (128 * QSTR + 64 * QSTR * 2 + 128 * PSTR + 384) * 4;  // 111.5 KB
    cudaFuncSetAttribute(attn_kernel, cudaFuncAttributeMaxDynamicSharedMemorySize, ATT_SMEM);
    attn_kernel<<<dim3(8, NB * NH), 256, ATT_SMEM>>>();               // 6

    wtrans_o_kernel<<<ND, 128>>>(Wo);                                 // 7
    ctxmix_kernel<<<NT, 128>>>(om);                                   // 8
    gemm_dp4a_kernel<<<dim3(9, 64), 256>>>(1, bo, out);               // 9
}

// round 16
// speedup vs baseline: 1.1484x; 1.1476x over previous
#include <cuda_runtime.h>
#include <cuda_fp16.h>
#include <math.h>

#define NB 8
#define NS 1024
#define ND 1152
#define NH 16
#define NHD 72
#define NL 32
#define NR 36
#define NT (NB*NS)
#define KW (ND/4)
#define BHS (NS*NHD)
#define WSTR 88
#define VSTR 72

typedef unsigned long long ull;
typedef unsigned short u16;
typedef unsigned int u32;

__device__ __align__(16) float  g_invA[NL*NL];
__device__ __align__(16) float  g_invB[NR*NR];
__device__ __align__(16) float  g_invVC[NHD*NHD];
__device__ __align__(16) float  g_invO[NH*NH];
__device__ double g_gj[4][72*144];

__device__ __align__(16) int    g_wq[3456*KW];
__device__ __align__(16) float  g_ws[3456];
__device__ __align__(16) float  g_bias[3456];
__device__ __align__(16) float  g_WvT[ND*ND];
__device__ __align__(16) int    g_woq[ND*KW];
__device__ __align__(16) float  g_wos[ND];

__device__ __align__(16) int    g_xq[NT*KW];
__device__ __align__(16) float  g_xs[NT];
__device__ __align__(16) float  g_q[NT*ND];
__device__ __align__(16) float  g_k[NT*ND];
__device__ __align__(16) float  g_v[NT*ND];
__device__ __align__(16) float  g_ctx[NT*ND];
__device__ __align__(16) int    g_cq[NT*KW];
__device__ __align__(16) float  g_cs[NT];

// ---- fp16 split helpers ----
__device__ __forceinline__ u16 f2h(float x) {
    return __half_as_ushort(__float2half_rn(x));
}
__device__ __forceinline__ float h2f(u16 h) {
    return __half2float(__ushort_as_half(h));
}
__device__ __forceinline__ u32 packh(u16 lo, u16 hi) { return (u32)lo | ((u32)hi << 16); }

__device__ __forceinline__ void mma16816(float* c, const u32* a, u32 b0, u32 b1) {
    asm volatile(
        "mma.sync.aligned.m16n8k16.row.col.f32.f16.f16.f32 "
        "{%0,%1,%2,%3}, {%4,%5,%6,%7}, {%8,%9}, {%0,%1,%2,%3};"
        : "+f"(c[0]), "+f"(c[1]), "+f"(c[2]), "+f"(c[3])
        : "r"(a[0]), "r"(a[1]), "r"(a[2]), "r"(a[3]), "r"(b0), "r"(b1));
}

// ---- compensated fp32 ----
__device__ __forceinline__ void df_mac(float a, float b, float& s, float& c) {
    float p = a * b;
    float e = fmaf(a, b, -p);
    float t = s + p;
    float bb = t - s;
    float err = (s - (t - bb)) + (p - bb);
    s = t; c += err + e;
}
__device__ __forceinline__ void df_mac2(float ahi, float alo, float b, float& s, float& c) {
    float p = ahi * b;
    float e = fmaf(ahi, b, -p);
    e = fmaf(alo, b, e);
    float t = s + p;
    float bb = t - s;
    float err = (s - (t - bb)) + (p - bb);
    s = t; c += err + e;
}
__device__ __forceinline__ float df_dequant(float a, float sx, float sw, float bias) {
    float p1 = a * sx;  float e1 = fmaf(a, sx, -p1);
    float p2 = p1 * sw; float e2 = fmaf(p1, sw, -p2);
    e2 = fmaf(e1, sw, e2);
    float t = p2 + bias;
    float bb = t - p2;
    float err = (p2 - (t - bb)) + (bias - bb);
    return t + (err + e2);
}

__device__ __forceinline__ int pack4q(float a, float b, float c, float d,
                                      float s, float lo, float hi) {
    int ia = (int)fminf(fmaxf(rintf(__fdiv_rn(a, s)), lo), hi);
    int ib = (int)fminf(fmaxf(rintf(__fdiv_rn(b, s)), lo), hi);
    int ic = (int)fminf(fmaxf(rintf(__fdiv_rn(c, s)), lo), hi);
    int id = (int)fminf(fmaxf(rintf(__fdiv_rn(d, s)), lo), hi);
    return (ia & 0xFF) | ((ib & 0xFF) << 8) | ((ic & 0xFF) << 16) | ((id & 0xFF) << 24);
}

__device__ __forceinline__ float block_max_abs_128(const float* Y, int n, int tid, float* red) {
    float mx = 0.f;
    for (int c = tid; c < n; c += 128) mx = fmaxf(mx, fabsf(Y[c]));
    red[tid] = mx;
    __syncthreads();
    for (int o = 64; o > 0; o >>= 1) {
        if (tid < o) red[tid] = fmaxf(red[tid], red[tid + o]);
        __syncthreads();
    }
    float r = red[0];
    __syncthreads();
    return r;
}

// ---- 1) inverses ----
__global__ void inv_kernel(const float* __restrict__ Asrc, const float* __restrict__ Bsrc,
                           const float* __restrict__ Vsrc, const float* __restrict__ Osrc) {
    int blk = blockIdx.x, tid = threadIdx.x;
    int n; const float* src; float* dst;
    if      (blk == 0) { n = NL;  src = Asrc; dst = g_invA;  }
    else if (blk == 1) { n = NR;  src = Bsrc; dst = g_invB;  }
    else if (blk == 2) { n = NHD; src = Vsrc; dst = g_invVC; }
    else               { n = NH;  src = Osrc; dst = g_invO;  }
    double* aug = g_gj[blk];
    int n2 = 2 * n;
    for (int idx = tid; idx < n * n2; idx += blockDim.x) {
        int i = idx / n2, j = idx - i * n2;
        aug[idx] = (j < n) ? (double)src[i * n + j] : ((j - n) == i ? 1.0 : 0.0);
    }
    __syncthreads();
    __shared__ int piv;
    for (int k = 0; k < n; k++) {
        if (tid == 0) {
            int p = k; double best = fabs(aug[k * n2 + k]);
            for (int i = k + 1; i < n; i++) {
                double v = fabs(aug[i * n2 + k]);
                if (v > best) { best = v; p = i; }
            }
            piv = p;
        }
        __syncthreads();
        if (piv != k) {
            for (int j = tid; j < n2; j += blockDim.x) {
                double t = aug[k * n2 + j];
                aug[k * n2 + j] = aug[piv * n2 + j];
                aug[piv * n2 + j] = t;
            }
        }
        __syncthreads();
        double pv = aug[k * n2 + k];
        __syncthreads();
        for (int j = tid; j < n2; j += blockDim.x) aug[k * n2 + j] /= pv;
        __syncthreads();
        for (int i = tid; i < n; i += blockDim.x) {
            if (i == k) continue;
            double f = aug[i * n2 + k];
            for (int j = 0; j < n2; j++) aug[i * n2 + j] -= f * aug[k * n2 + j];
        }
        __syncthreads();
    }
    for (int idx = tid; idx < n * n; idx += blockDim.x)
        dst[idx] = (float)aug[(idx / n) * n2 + n + (idx % n)];
}

// ---- 2) q/k/v weight kron ----
__global__ void wtrans_qkv_kernel(const float* __restrict__ Wq_, const float* __restrict__ bq_,
                                  const float* __restrict__ Wk_, const float* __restrict__ bk_,
                                  const float* __restrict__ Wv_, const float* __restrict__ ldg) {
    int which = blockIdx.y, i = blockIdx.x, tid = threadIdx.x;
    const float* W = (which == 0) ? Wq_ : (which == 1) ? Wk_ : Wv_;
    __shared__ float X[ND], Yf[ND];
    __shared__ float2 T1[ND];
    __shared__ float iA[NL*NL], iB[NR*NR], red[128];
    for (int c = tid; c < NL*NL; c += 128) iA[c] = g_invA[c];
    for (int c = tid; c < NR*NR; c += 128) iB[c] = g_invB[c];
    for (int c = tid; c < ND; c += 128) X[c] = W[(size_t)i * ND + c] * __frcp_rn(ldg[c]);
    __syncthreads();
    #pragma unroll
    for (int ob = 0; ob < 3; ob++) {
        int o0 = tid + ob * 384, o1 = o0 + 128, o2 = o0 + 256;
        int p0 = o0 / NR, r0 = o0 - p0 * NR;
        int p1 = o1 / NR, r1 = o1 - p1 * NR;
        int p2 = o2 / NR, r2 = o2 - p2 * NR;
        float s0 = 0.f, c0 = 0.f, s1 = 0.f, c1 = 0.f, s2 = 0.f, c2 = 0.f;
        #pragma unroll 8
        for (int l = 0; l < NL; l++) {
            df_mac(iA[p0 * NL + l], X[l * NR + r0], s0, c0);
            df_mac(iA[p1 * NL + l], X[l * NR + r1], s1, c1);
            df_mac(iA[p2 * NL + l], X[l * NR + r2], s2, c2);
        }
        T1[o0] = make_float2(s0, c0);
        T1[o1] = make_float2(s1, c1);
        T1[o2] = make_float2(s2, c2);
    }
    __syncthreads();
    #pragma unroll
    for (int ob = 0; ob < 3; ob++) {
        int o0 = tid + ob * 384, o1 = o0 + 128, o2 = o0 + 256;
        int p0 = o0 / NR, q0 = o0 - p0 * NR;
        int p1 = o1 / NR, q1 = o1 - p1 * NR;
        int p2 = o2 / NR, q2 = o2 - p2 * NR;
        float s0 = 0.f, c0 = 0.f, s1 = 0.f, c1 = 0.f, s2 = 0.f, c2 = 0.f;
        #pragma unroll 6
        for (int r = 0; r < NR; r++) {
            float2 t0 = T1[p0 * NR + r]; df_mac2(t0.x, t0.y, iB[q0 * NR + r], s0, c0);
            float2 t1 = T1[p1 * NR + r]; df_mac2(t1.x, t1.y, iB[q1 * NR + r], s1, c1);
            float2 t2 = T1[p2 * NR + r]; df_mac2(t2.x, t2.y, iB[q2 * NR + r], s2, c2);
        }
        Yf[o0] = s0 + c0; Yf[o1] = s1 + c1; Yf[o2] = s2 + c2;
    }
    __syncthreads();
    if (which == 2) {
        for (int c = tid; c < ND; c += 128) g_WvT[(size_t)i * ND + c] = Yf[c];
        return;
    }
    float mx = block_max_abs_128(Yf, ND, tid, red);
    float s = fmaxf(__fdiv_rn(mx, 7.0f), 1e-8f);
    int row = which * ND + i;
    for (int w = tid; w < KW; w += 128)
        g_wq[(size_t)row * KW + w] = pack4q(Yf[4*w], Yf[4*w+1], Yf[4*w+2], Yf[4*w+3], s, -8.f, 7.f);
    if (tid == 0) {
        g_ws[row] = s;
        g_bias[row] = (which == 0 ? bq_ : bk_)[i];
    }
}

// ---- 3) v weight vc mix ----
__global__ void wtrans_vmix_kernel(const float* __restrict__ vc, const float* __restrict__ bv) {
    int rr = blockIdx.x, tid = threadIdx.x;
    int h = rr / NHD, e = rr - h * NHD;
    __shared__ float Y[ND], red[128], vcol[NHD];
    for (int d = tid; d < NHD; d += 128) vcol[d] = vc[d * NHD + e];
    __syncthreads();
    float ys[9], yc[9];
    #pragma unroll
    for (int jj = 0; jj < 9; jj++) { ys[jj] = 0.f; yc[jj] = 0.f; }
    for (int d = 0; d < NHD; d++) {
        float vv = vcol[d];
        const float* row = &g_WvT[(size_t)(h * NHD + d) * ND];
        #pragma unroll
        for (int jj = 0; jj < 9; jj++) df_mac(row[tid + jj * 128], vv, ys[jj], yc[jj]);
    }
    #pragma unroll
    for (int jj = 0; jj < 9; jj++) Y[tid + jj * 128] = ys[jj] + yc[jj];
    __syncthreads();
    float mx = block_max_abs_128(Y, ND, tid, red);
    float s = fmaxf(__fdiv_rn(mx, 7.0f), 1e-8f);
    int row = 2 * ND + rr;
    for (int w = tid; w < KW; w += 128)
        g_wq[(size_t)row * KW + w] = pack4q(Y[4*w], Y[4*w+1], Y[4*w+2], Y[4*w+3], s, -8.f, 7.f);
    if (tid == 0) {
        g_ws[row] = s;
        double bt = 0.0;
        for (int d = 0; d < NHD; d++) bt += (double)bv[h * NHD + d] * (double)vcol[d];
        g_bias[row] = (float)bt;
    }
}

// ---- 4) output weight transform ----
__global__ void wtrans_o_kernel(const float* __restrict__ Wo_) {
    int o = blockIdx.x, tid = threadIdx.x;
    __shared__ float M[ND], Yf[ND], red[128];
    __shared__ float2 T[NH*NHD];
    __shared__ float iV[NHD*NHD], iO[NH*NH];
    for (int c = tid; c < NHD*NHD; c += 128) iV[c] = g_invVC[c];
    for (int c = tid; c < NH*NH; c += 128) iO[c] = g_invO[c];
    for (int c = tid; c < ND; c += 128) M[c] = Wo_[(size_t)o * ND + c];
    __syncthreads();
    #pragma unroll
    for (int ob = 0; ob < 3; ob++) {
        int i0 = tid + ob * 384, i1 = i0 + 128, i2 = i0 + 256;
        int g0 = i0 / NHD, e0 = i0 - g0 * NHD;
        int g1 = i1 / NHD, e1 = i1 - g1 * NHD;
        int g2 = i2 / NHD, e2 = i2 - g2 * NHD;
        float s0 = 0.f, c0 = 0.f, s1 = 0.f, c1 = 0.f, s2 = 0.f, c2 = 0.f;
        #pragma unroll 8
        for (int d = 0; d < NHD; d++) {
            df_mac(M[g0 * NHD + d], iV[e0 * NHD + d], s0, c0);
            df_mac(M[g1 * NHD + d], iV[e1 * NHD + d], s1, c1);
            df_mac(M[g2 * NHD + d], iV[e2 * NHD + d], s2, c2);
        }
        T[i0] = make_float2(s0, c0);
        T[i1] = make_float2(s1, c1);
        T[i2] = make_float2(s2, c2);
    }
    __syncthreads();
    #pragma unroll
    for (int ob = 0; ob < 3; ob++) {
        int i0 = tid + ob * 384, i1 = i0 + 128, i2 = i0 + 256;
        int h0 = i0 / NHD, e0 = i0 - h0 * NHD;
        int h1 = i1 / NHD, e1 = i1 - h1 * NHD;
        int h2 = i2 / NHD, e2 = i2 - h2 * NHD;
        float s0 = 0.f, c0 = 0.f, s1 = 0.f, c1 = 0.f, s2 = 0.f, c2 = 0.f;
        #pragma unroll
        for (int g = 0; g < NH; g++) {
            float2 t0 = T[g * NHD + e0]; df_mac2(t0.x, t0.y, iO[h0 * NH + g], s0, c0);
            float2 t1 = T[g * NHD + e1]; df_mac2(t1.x, t1.y, iO[h1 * NH + g], s1, c1);
            float2 t2 = T[g * NHD + e2]; df_mac2(t2.x, t2.y, iO[h2 * NH + g], s2, c2);
        }
        Yf[i0] = s0 + c0; Yf[i1] = s1 + c1; Yf[i2] = s2 + c2;
    }
    __syncthreads();
    float mx = block_max_abs_128(Yf, ND, tid, red);
    float s = fmaxf(__fdiv_rn(mx, 7.0f), 1e-8f);
    for (int w = tid; w < KW; w += 128)
        g_woq[(size_t)o * KW + w] = pack4q(Yf[4*w], Yf[4*w+1], Yf[4*w+2], Yf[4*w+3], s, -8.f, 7.f);
    if (tid == 0) g_wos[o] = s;
}

// ---- 5) activation kron + quant ----
__global__ void act_kernel(const float* __restrict__ hs, const float* __restrict__ ldg,
                           const float* __restrict__ lnA, const float* __restrict__ lnB) {
    int t = blockIdx.x, tid = threadIdx.x;
    __shared__ float X[ND], Yf[ND];
    __shared__ float2 T1[ND];
    __shared__ float A[NL*NL], Bm[NR*NR], red[128];
    for (int c = tid; c < NL*NL; c += 128) A[c] = lnA[c];
    for (int c = tid; c < NR*NR; c += 128) Bm[c] = lnB[c];
    for (int c = tid; c < ND; c += 128) X[c] = hs[(size_t)t * ND + c] * ldg[c];
    __syncthreads();
    #pragma unroll
    for (int ob = 0; ob < 3; ob++) {
        int o0 = tid + ob * 384, o1 = o0 + 128, o2 = o0 + 256;
        int p0 = o0 / NR, r0 = o0 - p0 * NR;
        int p1 = o1 / NR, r1 = o1 - p1 * NR;
        int p2 = o2 / NR, r2 = o2 - p2 * NR;
        float s0 = 0.f, c0 = 0.f, s1 = 0.f, c1 = 0.f, s2 = 0.f, c2 = 0.f;
        #pragma unroll 8
        for (int l = 0; l < NL; l++) {
            df_mac(A[l * NL + p0], X[l * NR + r0], s0, c0);
            df_mac(A[l * NL + p1], X[l * NR + r1], s1, c1);
            df_mac(A[l * NL + p2], X[l * NR + r2], s2, c2);
        }
        T1[o0] = make_float2(s0, c0);
        T1[o1] = make_float2(s1, c1);
        T1[o2] = make_float2(s2, c2);
    }
    __syncthreads();
    #pragma unroll
    for (int ob = 0; ob < 3; ob++) {
        int o0 = tid + ob * 384, o1 = o0 + 128, o2 = o0 + 256;
        int p0 = o0 / NR, q0 = o0 - p0 * NR;
        int p1 = o1 / NR, q1 = o1 - p1 * NR;
        int p2 = o2 / NR, q2 = o2 - p2 * NR;
        float s0 = 0.f, c0 = 0.f, s1 = 0.f, c1 = 0.f, s2 = 0.f, c2 = 0.f;
        #pragma unroll 6
        for (int r = 0; r < NR; r++) {
            float2 t0 = T1[p0 * NR + r]; df_mac2(t0.x, t0.y, Bm[r * NR + q0], s0, c0);
            float2 t1 = T1[p1 * NR + r]; df_mac2(t1.x, t1.y, Bm[r * NR + q1], s1, c1);
            float2 t2 = T1[p2 * NR + r]; df_mac2(t2.x, t2.y, Bm[r * NR + q2], s2, c2);
        }
        Yf[o0] = s0 + c0; Yf[o1] = s1 + c1; Yf[o2] = s2 + c2;
    }
    __syncthreads();
    float mx = block_max_abs_128(Yf, ND, tid, red);
    float s = fmaxf(__fdiv_rn(mx, 127.0f), 1e-8f);
    if (tid == 0) g_xs[t] = s;
    for (int w = tid; w < KW; w += 128)
        g_xq[(size_t)t * KW + w] = pack4q(Yf[4*w], Yf[4*w+1], Yf[4*w+2], Yf[4*w+3], s, -128.f, 127.f);
}

// ---- 6) dp4a GEMM ----
__global__ __launch_bounds__(256) void gemm_dp4a_kernel(int mode, const float* __restrict__ bias_ext,
                                                        float* __restrict__ outp) {
    __shared__ int Xs[16][128];
    __shared__ int Wsm[16][128];
    const int*   __restrict__ Xq  = mode ? g_cq  : g_xq;
    const float* __restrict__ xs  = mode ? g_cs  : g_xs;
    const int*   __restrict__ Wp  = mode ? g_woq : g_wq;
    const float* __restrict__ wsp = mode ? g_wos : g_ws;
    int m0 = blockIdx.y * 128, n0 = blockIdx.x * 128;
    int tid = threadIdx.x;
    int acc[8][8];
    #pragma unroll
    for (int i = 0; i < 8; i++)
        #pragma unroll
        for (int j = 0; j < 8; j++) acc[i][j] = 0;
    int r = tid >> 2, wg = (tid & 3) << 2;
    int ty = tid >> 4, tx = tid & 15;
    for (int kt = 0; kt < 18; kt++) {
        #pragma unroll
        for (int half = 0; half < 2; half++) {
            int row = r + (half << 6);
            int4 xv = *(const int4*)&Xq[(size_t)(m0 + row) * KW + kt * 16 + wg];
            Xs[wg + 0][row] = xv.x; Xs[wg + 1][row] = xv.y;
            Xs[wg + 2][row] = xv.z; Xs[wg + 3][row] = xv.w;
            int4 wv = *(const int4*)&Wp[(size_t)(n0 + row) * KW + kt * 16 + wg];
            Wsm[wg + 0][row] = wv.x; Wsm[wg + 1][row] = wv.y;
            Wsm[wg + 2][row] = wv.z; Wsm[wg + 3][row] = wv.w;
        }
        __syncthreads();
        #pragma unroll 4
        for (int kk = 0; kk < 16; kk++) {
            int4 xa = *(const int4*)&Xs[kk][ty << 3];
            int4 xb = *(const int4*)&Xs[kk][(ty << 3) + 4];
            int4 wa = *(const int4*)&Wsm[kk][tx << 3];
            int4 wb = *(const int4*)&Wsm[kk][(tx << 3) + 4];
            int xv[8] = {xa.x, xa.y, xa.z, xa.w, xb.x, xb.y, xb.z, xb.w};
            int wv[8] = {wa.x, wa.y, wa.z, wa.w, wb.x, wb.y, wb.z, wb.w};
            #pragma unroll
            for (int i = 0; i < 8; i++)
                #pragma unroll
                for (int j = 0; j < 8; j++)
                    acc[i][j] = __dp4a(xv[i], wv[j], acc[i][j]);
        }
        __syncthreads();
    }
    #pragma unroll
    for (int i = 0; i < 8; i++) {
        int m = m0 + (ty << 3) + i;
        float sx = xs[m];
        #pragma unroll
        for (int j = 0; j < 8; j++) {
            int n = n0 + (tx << 3) + j;
            if (mode) {
                float val = df_dequant((float)acc[i][j], sx, wsp[n], bias_ext[n]);
                outp[(size_t)m * ND + n] = val;
            } else {
                float val = df_dequant((float)acc[i][j], sx, wsp[n], g_bias[n]);
                int which = n / ND;
                int jj = n - which * ND;
                int h = jj / NHD, hd = jj - h * NHD;
                int b = m >> 10, sidx = m & 1023;
                float* dst = (which == 0) ? g_q : (which == 1) ? g_k : g_v;
                dst[((size_t)((b << 4) + h) * NS + sidx) * NHD + hd] = val;
            }
        }
    }
}

// ---- 7) attention: fp16x2-split tensor-core flash attention ----
// 256 thr = 8 warps; warp w owns q rows qt*128 + w*16..+15. Softmax warp-local.
__global__ __launch_bounds__(256, 2) void attn_mma_kernel() {
    extern __shared__ u16 smu[];
    u16* Qh = smu;                        // 128 x WSTR
    u16* Ql = Qh + 128 * WSTR;
    u16* Kh = Ql + 128 * WSTR;            // 64 x WSTR
    u16* Kl = Kh + 64 * WSTR;
    u16* Vh = Kl + 64 * WSTR;             // 72 x VSTR (transposed)
    u16* Vl = Vh + 72 * VSTR;
    int bh = blockIdx.y, qt = blockIdx.x, tid = threadIdx.x;
    int w = tid >> 5, lane = tid & 31;
    int grp = lane >> 2, qu = lane & 3;
    const float* Qp = g_q + (size_t)bh * BHS + (size_t)qt * 128 * NHD;
    const float* Kp = g_k + (size_t)bh * BHS;
    const float* Vp = g_v + (size_t)bh * BHS;

    for (int idx = tid; idx < 128 * 80; idx += 256) {
        int row = idx / 80, d = idx - row * 80;
        float x = (d < 72) ? Qp[row * NHD + d] : 0.f;
        u16 hb = f2h(x);
        Qh[row * WSTR + d] = hb;
        Ql[row * WSTR + d] = f2h(x - h2f(hb));
    }
    float dacc[9][4];
    #pragma unroll
    for (int nt = 0; nt < 9; nt++)
        #pragma unroll
        for (int z = 0; z < 4; z++) dacc[nt][z] = 0.f;
    float m0 = -1e30f, m1 = -1e30f, l0 = 0.f, l1 = 0.f;
    __syncthreads();

    for (int kt0 = 0; kt0 < NS; kt0 += 64) {
        for (int idx = tid; idx < 64 * 80; idx += 256) {
            int row = idx / 80, d = idx - row * 80;
            float x = (d < 72) ? Kp[(kt0 + row) * NHD + d] : 0.f;
            u16 hb = f2h(x);
            Kh[row * WSTR + d] = hb;
            Kl[row * WSTR + d] = f2h(x - h2f(hb));
        }
        for (int idx = tid; idx < 64 * 72; idx += 256) {
            int ks = idx / 72, c = idx - ks * 72;
            float x = Vp[(kt0 + ks) * NHD + c];
            u16 hb = f2h(x);
            Vh[c * VSTR + ks] = hb;
            Vl[c * VSTR + ks] = f2h(x - h2f(hb));
        }
        __syncthreads();

        // scores
        float sc[8][4];
        #pragma unroll
        for (int nt = 0; nt < 8; nt++)
            #pragma unroll
            for (int z = 0; z < 4; z++) sc[nt][z] = 0.f;
        int arow = w * 16 + grp;
        #pragma unroll
        for (int ks = 0; ks < 5; ks++) {
            int dbase = ks * 16 + 2 * qu;
            u32 ah[4], al[4];
            ah[0] = *(const u32*)&Qh[arow * WSTR + dbase];
            ah[1] = *(const u32*)&Qh[(arow + 8) * WSTR + dbase];
            ah[2] = *(const u32*)&Qh[arow * WSTR + dbase + 8];
            ah[3] = *(const u32*)&Qh[(arow + 8) * WSTR + dbase + 8];
            al[0] = *(const u32*)&Ql[arow * WSTR + dbase];
            al[1] = *(const u32*)&Ql[(arow + 8) * WSTR + dbase];
            al[2] = *(const u32*)&Ql[arow * WSTR + dbase + 8];
            al[3] = *(const u32*)&Ql[(arow + 8) * WSTR + dbase + 8];
            #pragma unroll
            for (int nt = 0; nt < 8; nt++) {
                int brow = nt * 8 + grp;
                u32 b0 = *(const u32*)&Kh[brow * WSTR + dbase];
                u32 b1 = *(const u32*)&Kh[brow * WSTR + dbase + 8];
                u32 c0 = *(const u32*)&Kl[brow * WSTR + dbase];
                u32 c1 = *(const u32*)&Kl[brow * WSTR + dbase + 8];
                mma16816(sc[nt], ah, b0, b1);
                mma16816(sc[nt], ah, c0, c1);
                mma16816(sc[nt], al, b0, b1);
            }
        }
        // warp-local online softmax (rows grp and grp+8)
        float rm0 = -1e30f, rm1 = -1e30f;
        #pragma unroll
        for (int nt = 0; nt < 8; nt++) {
            rm0 = fmaxf(rm0, fmaxf(sc[nt][0], sc[nt][1]));
            rm1 = fmaxf(rm1, fmaxf(sc[nt][2], sc[nt][3]));
        }
        rm0 = fmaxf(rm0, __shfl_xor_sync(0xffffffffu, rm0, 1));
        rm0 = fmaxf(rm0, __shfl_xor_sync(0xffffffffu, rm0, 2));
        rm1 = fmaxf(rm1, __shfl_xor_sync(0xffffffffu, rm1, 1));
        rm1 = fmaxf(rm1, __shfl_xor_sync(0xffffffffu, rm1, 2));
        float mn0 = fmaxf(m0, rm0), mn1 = fmaxf(m1, rm1);
        float f0 = __expf(m0 - mn0), f1 = __expf(m1 - mn1);
        m0 = mn0; m1 = mn1;
        float rs0 = 0.f, rs1 = 0.f;
        #pragma unroll
        for (int nt = 0; nt < 8; nt++) {
            sc[nt][0] = __expf(sc[nt][0] - mn0);
            sc[nt][1] = __expf(sc[nt][1] - mn0);
            sc[nt][2] = __expf(sc[nt][2] - mn1);
            sc[nt][3] = __expf(sc[nt][3] - mn1);
            rs0 += sc[nt][0] + sc[nt][1];
            rs1 += sc[nt][2] + sc[nt][3];
        }
        rs0 += __shfl_xor_sync(0xffffffffu, rs0, 1);
        rs0 += __shfl_xor_sync(0xffffffffu, rs0, 2);
        rs1 += __shfl_xor_sync(0xffffffffu, rs1, 1);
        rs1 += __shfl_xor_sync(0xffffffffu, rs1, 2);
        l0 = l0 * f0 + rs0;
        l1 = l1 * f1 + rs1;
        #pragma unroll
        for (int nt = 0; nt < 9; nt++) {
            dacc[nt][0] *= f0; dacc[nt][1] *= f0;
            dacc[nt][2] *= f1; dacc[nt][3] *= f1;
        }
        // PV: A = P frags from registers (C-layout == A-layout), B = Vt frags
        #pragma unroll
        for (int kc = 0; kc < 4; kc++) {
            u32 ah[4], al[4];
            {
                float p00 = sc[2*kc][0],   p01 = sc[2*kc][1];
                float p10 = sc[2*kc][2],   p11 = sc[2*kc][3];
                float p20 = sc[2*kc+1][0], p21 = sc[2*kc+1][1];
                float p30 = sc[2*kc+1][2], p31 = sc[2*kc+1][3];
                u16 h00 = f2h(p00), h01 = f2h(p01);
                u16 h10 = f2h(p10), h11 = f2h(p11);
                u16 h20 = f2h(p20), h21 = f2h(p21);
                u16 h30 = f2h(p30), h31 = f2h(p31);
                ah[0] = packh(h00, h01); ah[1] = packh(h10, h11);
                ah[2] = packh(h20, h21); ah[3] = packh(h30, h31);
                al[0] = packh(f2h(p00 - h2f(h00)), f2h(p01 - h2f(h01)));
                al[1] = packh(f2h(p10 - h2f(h10)), f2h(p11 - h2f(h11)));
                al[2] = packh(f2h(p20 - h2f(h20)), f2h(p21 - h2f(h21)));
                al[3] = packh(f2h(p30 - h2f(h30)), f2h(p31 - h2f(h31)));
            }
            int kb = kc * 16 + 2 * qu;
            #pragma unroll
            for (int nt = 0; nt < 9; nt++) {
                int vrow = nt * 8 + grp;
                u32 b0 = *(const u32*)&Vh[vrow * VSTR + kb];
                u32 b1 = *(const u32*)&Vh[vrow * VSTR + kb + 8];
                u32 c0 = *(const u32*)&Vl[vrow * VSTR + kb];
                u32 c1 = *(const u32*)&Vl[vrow * VSTR + kb + 8];
                mma16816(dacc[nt], ah, b0, b1);
                mma16816(dacc[nt], ah, c0, c1);
                mma16816(dacc[nt], al, b0, b1);
            }
        }
        __syncthreads();
    }
    // write ctx (B,S,H,HD)
    int h = bh & 15, b = bh >> 4;
    int r0 = qt * 128 + w * 16 + grp;
    #pragma unroll
    for (int half = 0; half < 2; half++) {
        int sidx = r0 + half * 8;
        float l = half ? l1 : l0;
        size_t base = ((size_t)(b * NS + sidx) * NH + h) * NHD;
        #pragma unroll
        for (int nt = 0; nt < 9; nt++) {
            int col = nt * 8 + 2 * qu;
            float2 o2;
            o2.x = __fdiv_rn(dacc[nt][half * 2 + 0], l);
            o2.y = __fdiv_rn(dacc[nt][half * 2 + 1], l);
            *(float2*)&g_ctx[base + col] = o2;
        }
    }
}

// ---- 8) head mix + quant ----
__global__ void ctxmix_kernel(const float* __restrict__ om) {
    int t = blockIdx.x, tid = threadIdx.x;
    __shared__ float C[ND], Y[ND], O[NH*NH], red[128];
    for (int c = tid; c < NH*NH; c += 128) O[c] = om[c];
    for (int c = tid; c < ND; c += 128) C[c] = g_ctx[(size_t)t * ND + c];
    __syncthreads();
    #pragma unroll
    for (int ob = 0; ob < 3; ob++) {
        int o0 = tid + ob * 384, o1 = o0 + 128, o2 = o0 + 256;
        int h0 = o0 / NHD, d0 = o0 - h0 * NHD;
        int h1 = o1 / NHD, d1 = o1 - h1 * NHD;
        int h2 = o2 / NHD, d2 = o2 - h2 * NHD;
        float s0 = 0.f, c0 = 0.f, s1 = 0.f, c1 = 0.f, s2 = 0.f, c2 = 0.f;
        #pragma unroll
        for (int g = 0; g < NH; g++) {
            df_mac(O[g * NH + h0], C[g * NHD + d0], s0, c0);
            df_mac(O[g * NH + h1], C[g * NHD + d1], s1, c1);
            df_mac(O[g * NH + h2], C[g * NHD + d2], s2, c2);
        }
        Y[o0] = s0 + c0; Y[o1] = s1 + c1; Y[o2] = s2 + c2;
    }
    __syncthreads();
    float mx = block_max_abs_128(Y, ND, tid, red);
    float s = fmaxf(__fdiv_rn(mx, 127.0f), 1e-8f);
    if (tid == 0) g_cs[t] = s;
    for (int w = tid; w < KW; w += 128)
        g_cq[(size_t)t * KW + w] = pack4q(Y[4*w], Y[4*w+1], Y[4*w+2], Y[4*w+3], s, -128.f, 127.f);
}

// ---- launch ----
extern "C" void kernel_launch(void* const* d_in, const int* in_sizes, int n_in,
                              void* d_out, int out_size) {
    const float* hs  = (const float*)d_in[0];
    const float* Wq  = (const float*)d_in[1];
    const float* bq  = (const float*)d_in[2];
    const float* Wk  = (const float*)d_in[3];
    const float* bk  = (const float*)d_in[4];
    const float* Wv  = (const float*)d_in[5];
    const float* bv  = (const float*)d_in[6];
    const float* Wo  = (const float*)d_in[7];
    const float* bo  = (const float*)d_in[8];
    const float* lnA = (const float*)d_in[9];
    const float* lnB = (const float*)d_in[10];
    const float* ldg = (const float*)d_in[11];
    const float* vc  = (const float*)d_in[12];
    const float* om  = (const float*)d_in[13];
    float* out = (float*)d_out;

    inv_kernel<<<4, 128>>>(lnA, lnB, vc, om);
    wtrans_qkv_kernel<<<dim3(ND, 3), 128>>>(Wq, bq, Wk, bk, Wv, ldg);
    wtrans_vmix_kernel<<<ND, 128>>>(vc, bv);
    act_kernel<<<NT, 128>>>(hs, ldg, lnA, lnB);
    gemm_dp4a_kernel<<<dim3(27, 64), 256>>>(0, nullptr, nullptr);

    const int ATT_SMEM = (2 * 128 * WSTR + 2 * 64 * WSTR + 2 * 72 * VSTR) * 2;  // 88.3 KB
    cudaFuncSetAttribute(attn_mma_kernel, cudaFuncAttributeMaxDynamicSharedMemorySize, ATT_SMEM);
    attn_mma_kernel<<<dim3(8, NB * NH), 256, ATT_SMEM>>>();

    wtrans_o_kernel<<<ND, 128>>>(Wo);
    ctxmix_kernel<<<NT, 128>>>(om);
    gemm_dp4a_kernel<<<dim3(9, 64), 256>>>(1, bo, out);
}